// round 14
// baseline (speedup 1.0000x reference)
#include <cuda_runtime.h>
#include <cuda_bf16.h>
#include <math.h>
#include <stdint.h>

#define NN 64
#define BB 32
#define HH 512
#define KK 128
#define VV 32000
#define TT 256
#define SS 32
#define AA 5
#define AN 20
#define M2 (NN*BB)          // 2048 rows
#define CIN (3*HH+KK)       // 1664
#define GIN (2*HH+AN)       // 1044
#define NASP 2000
#define GRU_BLOCKS 128
#define SIDE_BLOCKS 20

// ---------------- scratch (static device globals; no runtime alloc) ----------------
__device__ __align__(16) float g_gi[M2*3*HH];
__device__ __align__(16) float g_hA[HH*BB];
__device__ __align__(16) float g_hB[HH*BB];
__device__ __align__(16) float g_rnn[M2*HH];
__device__ __align__(16) float g_u1[HH];
__device__ __align__(16) float g_u3[HH];
__device__ float g_bv[2];
__device__ float g_a1[M2], g_a3[M2];
__device__ float g_c1[TT*BB], g_c2[SS*BB], g_c3[AA*BB];
__device__ __align__(16) float g_ctx1[M2*HH];
__device__ __align__(16) float g_ctx2[M2*HH];
__device__ __align__(16) float g_ctx3[M2*KK];
__device__ __align__(16) float g_cout[M2*HH];
__device__ __align__(16) uint32_t g_wt[VV*HH];      // 65.5 MB pre-rounded, fragment-packed W
__device__ __align__(16) uint32_t g_at[M2*HH];      // 4 MB fragment-packed A
__device__ float g_e4[BB*AN];
__device__ int g_first[NASP], g_next[NASP];
__device__ __align__(128) unsigned g_flag[GRU_BLOCKS*32] = {0};

// ---------------- contention-free flag barrier (GRU blocks only; monotonic) ----------------
__device__ __forceinline__ void gru_barrier(int bk, unsigned step) {
    __syncthreads();
    if (threadIdx.x == 0) {
        asm volatile("st.release.gpu.global.u32 [%0], %1;"
                     :: "l"(&g_flag[bk*32]), "r"(step) : "memory");
    }
    if (threadIdx.x < GRU_BLOCKS) {
        unsigned v;
        do {
            asm volatile("ld.acquire.gpu.global.u32 %0, [%1];"
                         : "=r"(v) : "l"(&g_flag[threadIdx.x*32]) : "memory");
        } while (v < step);
    }
    __syncthreads();
}

// ---------------- helpers ----------------
__device__ __forceinline__ uint32_t smem_u32(const void* p) {
    uint32_t a;
    asm("{ .reg .u64 t; cvta.to.shared.u64 t, %1; cvt.u32.u64 %0, t; }" : "=r"(a) : "l"(p));
    return a;
}
__device__ __forceinline__ uint32_t f2tf(float x) {
    uint32_t u; asm("cvt.rna.tf32.f32 %0, %1;" : "=r"(u) : "f"(x)); return u;
}
__device__ __forceinline__ void split_tf32(float x, uint32_t& hi, uint32_t& lo) {
    hi = f2tf(x);
    float r = x - __uint_as_float(hi);
    lo = f2tf(r);
}
__device__ __forceinline__ void mma_tf32(float& c0, float& c1, float& c2, float& c3,
                                         uint32_t a0, uint32_t a1, uint32_t a2, uint32_t a3,
                                         uint32_t b0, uint32_t b1) {
    asm volatile("mma.sync.aligned.m16n8k8.row.col.f32.tf32.tf32.f32 "
                 "{%0,%1,%2,%3},{%4,%5,%6,%7},{%8,%9},{%0,%1,%2,%3};"
                 : "+f"(c0), "+f"(c1), "+f"(c2), "+f"(c3)
                 : "r"(a0), "r"(a1), "r"(a2), "r"(a3), "r"(b0), "r"(b1));
}
__device__ __forceinline__ void cpa16(uint32_t saddr, const void* gaddr) {
    asm volatile("cp.async.cg.shared.global [%0], [%1], 16;" :: "r"(saddr), "l"(gaddr));
}

// ---------------- kernels ----------------

// A pack for the big GEMM
__global__ void k_pack_a(const float* __restrict__ A) {
    long i = (long)blockIdx.x * 256 + threadIdx.x;
    if (i >= (long)(M2/128)*64*8*32) return;
    int lane = (int)(i & 31), mf = (int)((i >> 5) & 7), s = (int)((i >> 8) & 63);
    long mb = i >> 14;
    int lq = lane >> 2, lr = lane & 3;
    int k = s*8 + lr;
    long me = mb*128 + mf*16 + lq;
    uint4 v;
    v.x = f2tf(A[me*HH + k]);
    v.y = f2tf(A[(me+8)*HH + k]);
    v.z = f2tf(A[me*HH + k + 4]);
    v.w = f2tf(A[(me+8)*HH + k + 4]);
    ((uint4*)g_at)[i] = v;
}

// ---------------- packed tf32 GEMM: C[M2,VV] = A[M2,HH] * W[VV,HH]^T + bias ----------------
__global__ __launch_bounds__(128, 2)
void k_gemm_tf32p(const uint4* __restrict__ At, const uint4* __restrict__ Wt,
                  const float* __restrict__ bias, float* __restrict__ C) {
    __shared__ __align__(16) uint4 As[2][512];
    __shared__ __align__(16) uint4 Bs[2][512];
    int tid = threadIdx.x;
    int warp = tid >> 5, lane = tid & 31;
    int wm = warp & 1, wnp = warp >> 1;
    int lq = lane >> 2, lr = lane & 3;
    int m0 = blockIdx.x * 128, n0 = blockIdx.y * 128;
    const uint4* Ab = At + (long)blockIdx.x * 16384;
    const uint4* Bb = Wt + (long)blockIdx.y * 16384;

    float acc[4][8][4];
#pragma unroll
    for (int i = 0; i < 4; i++)
#pragma unroll
        for (int j = 0; j < 8; j++)
#pragma unroll
            for (int c = 0; c < 4; c++) acc[i][j][c] = 0.f;

#pragma unroll
    for (int i = 0; i < 4; i++) {
        cpa16(smem_u32(&As[0][i*128 + tid]), Ab + i*128 + tid);
        cpa16(smem_u32(&Bs[0][i*128 + tid]), Bb + i*128 + tid);
    }
    asm volatile("cp.async.commit_group;");

    int buf = 0;
    const int NK = HH / 16;
    for (int c = 0; c < NK; c++) {
        asm volatile("cp.async.wait_group 0;" ::: "memory");
        __syncthreads();
        if (c + 1 < NK) {
            const uint4* an = Ab + (c+1)*512;
            const uint4* bn = Bb + (c+1)*512;
#pragma unroll
            for (int i = 0; i < 4; i++) {
                cpa16(smem_u32(&As[buf^1][i*128 + tid]), an + i*128 + tid);
                cpa16(smem_u32(&Bs[buf^1][i*128 + tid]), bn + i*128 + tid);
            }
            asm volatile("cp.async.commit_group;");
        }
#pragma unroll
        for (int kk = 0; kk < 2; kk++) {
            uint4 av[4], bv[4];
#pragma unroll
            for (int ms = 0; ms < 4; ms++)
                av[ms] = As[buf][kk*256 + (wm*4 + ms)*32 + lane];
#pragma unroll
            for (int p = 0; p < 4; p++)
                bv[p] = Bs[buf][kk*256 + (wnp*4 + p)*32 + lane];
#pragma unroll
            for (int ms = 0; ms < 4; ms++)
#pragma unroll
                for (int p = 0; p < 4; p++) {
                    mma_tf32(acc[ms][2*p][0], acc[ms][2*p][1], acc[ms][2*p][2], acc[ms][2*p][3],
                             av[ms].x, av[ms].y, av[ms].z, av[ms].w, bv[p].x, bv[p].y);
                    mma_tf32(acc[ms][2*p+1][0], acc[ms][2*p+1][1], acc[ms][2*p+1][2], acc[ms][2*p+1][3],
                             av[ms].x, av[ms].y, av[ms].z, av[ms].w, bv[p].z, bv[p].w);
                }
        }
        buf ^= 1;
    }
#pragma unroll
    for (int ms = 0; ms < 4; ms++) {
        int row = m0 + wm*64 + ms*16 + lq;
#pragma unroll
        for (int ns = 0; ns < 8; ns++) {
            int col = n0 + wnp*64 + ns*8 + lr*2;
            float b0 = bias[col], b1 = bias[col+1];
            *(float2*)(C + (long)row*VV + col)     = make_float2(acc[ms][ns][0] + b0, acc[ms][ns][1] + b1);
            *(float2*)(C + (long)(row+8)*VV + col) = make_float2(acc[ms][ns][2] + b0, acc[ms][ns][3] + b1);
        }
    }
}

// ---------------- mega kernel: persistent GRU (0..127) + side work (128..147) ----------------
__global__ __launch_bounds__(512, 1)
void k_gru_all(const float* __restrict__ lasth, const float* __restrict__ Whh,
               const float* __restrict__ bhh, float* __restrict__ hid,
               const float* __restrict__ outW,
               const float* __restrict__ attnW, const float* __restrict__ attnv,
               const float* __restrict__ attnb, const float* __restrict__ attrW,
               const float* __restrict__ attrv, const float* __restrict__ attrb,
               const float* __restrict__ enc4, const float* __restrict__ projW,
               const float* __restrict__ projb, const int* __restrict__ asp,
               const float* __restrict__ enc1, const float* __restrict__ enc2,
               const float* __restrict__ enc3) {
    extern __shared__ __align__(16) float dsm[];
    int tid = threadIdx.x, bk = blockIdx.x;

    if (bk >= GRU_BLOCKS) {
        // ===================== side work on 20 spare SMs =====================
        int sb = bk - GRU_BLOCKS;
        float* su1e = dsm;            // [512]
        float* su3e = dsm + 512;      // [128]
        int*   sid  = (int*)(dsm + 1024);

        // (1) per-block u1e/u3e (coalesced column loop; attnW L2-resident)
        if (tid < HH) {
            float a1e = 0.f, a3e = 0.f;
            bool has3 = (tid < KK);
            for (int h = 0; h < HH; h++) {
                float vv = attnv[h];
                a1e += attnW[(long)h*(2*HH) + HH + tid]*vv;
                if (has3) a3e += attrW[(long)h*(HH+KK) + HH + tid]*attrv[h];
            }
            su1e[tid] = a1e;
            if (has3) su3e[tid] = a3e;
        }
        __syncthreads();

        // (2) per-block special tasks
        if (sb == 0) {              // e4 projection
            for (int i = tid; i < BB*AN; i += 512) {
                int b = i / AN, j = i - b*AN;
                float s = projb[j];
                for (int k = 0; k < AN; k++) s += enc4[(0*BB + b)*AN + k]*projW[j*2*AN + k];
                for (int k = 0; k < AN; k++) s += enc4[(1*BB + b)*AN + k]*projW[j*2*AN + AN + k];
                g_e4[i] = s;
            }
        } else if (sb == 1) {       // duplicate chain
            for (int k = tid; k < NASP; k += 512) sid[k] = asp[k];
            __syncthreads();
            for (int j = tid; j < NASP; j += 512) {
                int v = sid[j];
                int fst = 1, nxt = -1;
                for (int j2 = 0; j2 < NASP; j2++) {
                    int w = sid[j2];
                    if (w == v) {
                        if (j2 < j) fst = 0;
                        else if (j2 > j && nxt < 0) nxt = j2;
                    }
                }
                g_first[j] = fst;
                g_next[j]  = nxt;
            }
        } else if (sb == 2) {       // u1 columns (coalesced)
            if (tid < HH) {
                float s = 0.f;
                for (int h = 0; h < HH; h++) s += attnW[(long)h*(2*HH) + tid]*attnv[h];
                g_u1[tid] = s;
            }
        } else if (sb == 3) {       // u3 columns
            if (tid < HH) {
                float s = 0.f;
                for (int h = 0; h < HH; h++) s += attrW[(long)h*(HH+KK) + tid]*attrv[h];
                g_u3[tid] = s;
            }
        } else if (sb == 4) {       // b.v scalars
            int w = tid >> 5, lane = tid & 31;
            if (w < 2) {
                const float* bp = w ? attrb : attnb;
                const float* vp = w ? attrv : attnv;
                float s = 0.f;
                for (int h = lane; h < HH; h += 32) s += bp[h]*vp[h];
#pragma unroll
                for (int o = 16; o > 0; o >>= 1) s += __shfl_xor_sync(0xffffffffu, s, o);
                if (lane == 0) g_bv[w] = s;
            }
        }

        // (3) c-dots partitioned across side blocks (warp per output)
        {
            const int TC1 = TT*BB, TC2 = TC1 + SS*BB, TC3 = TC2 + AA*BB;
            int gw2 = sb*16 + (tid >> 5);
            int lane = tid & 31;
            for (int t = gw2; t < TC3; t += SIDE_BLOCKS*16) {
                const float* x; const float* u = su1e; float* dst; int len = HH;
                if (t < TC1)      { x = enc1 + (long)t*HH;        dst = g_c1 + t; }
                else if (t < TC2) { x = enc2 + (long)(t-TC1)*HH;  dst = g_c2 + (t-TC1); }
                else              { x = enc3 + (long)(t-TC2)*KK;  dst = g_c3 + (t-TC2); u = su3e; len = KK; }
                float s = 0.f;
                for (int k = lane; k < len; k += 32) s += x[k]*u[k];
#pragma unroll
                for (int o = 16; o > 0; o >>= 1) s += __shfl_xor_sync(0xffffffffu, s, o);
                if (lane == 0) *dst = s;
            }
        }

        // (4) W fragment pack (grid-strided; bulk of shadow time)
        const long TOTW = (long)(VV/128)*64*8*32;
        for (long i = (long)sb*512 + tid; i < TOTW; i += (long)SIDE_BLOCKS*512) {
            int lane = (int)(i & 31), fp = (int)((i >> 5) & 7), s = (int)((i >> 8) & 63);
            long nb = i >> 14;
            int lq = lane >> 2, lr = lane & 3;
            int k = s*8 + lr;
            long ne = nb*128 + fp*16 + lq;
            uint4 v;
            v.x = f2tf(outW[ne*HH + k]);
            v.y = f2tf(outW[ne*HH + k + 4]);
            v.z = f2tf(outW[(ne+8)*HH + k]);
            v.w = f2tf(outW[(ne+8)*HH + k + 4]);
            ((uint4*)g_wt)[i] = v;
        }
        return;
    }

    // ===================== persistent GRU =====================
    float* sw   = dsm;                    // 6144
    float* sh   = dsm + 6144;             // 16384
    float* part = dsm + 6144 + 16384;     // 3072
    float* sbv  = part + 3072;            // 12

    int b  = tid & 31;
    int ju = (tid >> 5) & 1;
    int kq = tid >> 6;

    for (int r = 0; r < 12; r++) {
        int g = r / 4, j = r % 4;
        int rowi = g*HH + bk*4 + j;
        for (int k = tid; k < HH; k += 512) sw[(g*4 + j)*HH + k] = Whh[(long)rowi*HH + k];
    }
    if (tid < 12) sbv[tid] = bhh[(tid/4)*HH + bk*4 + (tid%4)];

    if (tid < 128) {
        int idx = bk*128 + tid;
        int k = idx >> 5, bb = idx & 31;
        __stcg(&g_hA[idx], lasth[bb*HH + k]);
    }
    gru_barrier(bk, 1u);

    float* hp = g_hA;
    float* hc = g_hB;
    int u0 = ju*2;
    const float* wr0 = sw + (0*4 + u0    )*HH;
    const float* wr1 = sw + (0*4 + u0 + 1)*HH;
    const float* wz0 = sw + (1*4 + u0    )*HH;
    const float* wz1 = sw + (1*4 + u0 + 1)*HH;
    const float* wn0 = sw + (2*4 + u0    )*HH;
    const float* wn1 = sw + (2*4 + u0 + 1)*HH;
    int k0 = kq * 64;

    for (int n = 0; n < NN; n++) {
#pragma unroll
        for (int i = 0; i < 8; i++) {
            int f = tid + i*512;
            float4 v = __ldcg((const float4*)hp + f);
            *(float4*)(sh + 4*f) = v;
        }
        __syncthreads();

        float sr0 = 0.f, sz0 = 0.f, sn0 = 0.f;
        float sr1 = 0.f, sz1 = 0.f, sn1 = 0.f;
#pragma unroll 4
        for (int k = k0; k < k0 + 64; k += 4) {
            float h0 = sh[(k+0)*BB + b];
            float h1 = sh[(k+1)*BB + b];
            float h2 = sh[(k+2)*BB + b];
            float h3 = sh[(k+3)*BB + b];
            float4 a;
            a = *(const float4*)(wr0 + k); sr0 += a.x*h0 + a.y*h1 + a.z*h2 + a.w*h3;
            a = *(const float4*)(wz0 + k); sz0 += a.x*h0 + a.y*h1 + a.z*h2 + a.w*h3;
            a = *(const float4*)(wn0 + k); sn0 += a.x*h0 + a.y*h1 + a.z*h2 + a.w*h3;
            a = *(const float4*)(wr1 + k); sr1 += a.x*h0 + a.y*h1 + a.z*h2 + a.w*h3;
            a = *(const float4*)(wz1 + k); sz1 += a.x*h0 + a.y*h1 + a.z*h2 + a.w*h3;
            a = *(const float4*)(wn1 + k); sn1 += a.x*h0 + a.y*h1 + a.z*h2 + a.w*h3;
        }
        part[((0*4 + u0    )*8 + kq)*32 + b] = sr0;
        part[((1*4 + u0    )*8 + kq)*32 + b] = sz0;
        part[((2*4 + u0    )*8 + kq)*32 + b] = sn0;
        part[((0*4 + u0 + 1)*8 + kq)*32 + b] = sr1;
        part[((1*4 + u0 + 1)*8 + kq)*32 + b] = sz1;
        part[((2*4 + u0 + 1)*8 + kq)*32 + b] = sn1;
        __syncthreads();

        if (kq < 2) {
            int jgl = u0 + kq;
            int jg  = bk*4 + jgl;
            float sr = 0.f, sz = 0.f, sn = 0.f;
#pragma unroll
            for (int q = 0; q < 8; q++) {
                sr += part[((0*4 + jgl)*8 + q)*32 + b];
                sz += part[((1*4 + jgl)*8 + q)*32 + b];
                sn += part[((2*4 + jgl)*8 + q)*32 + b];
            }
            float hold = sh[jg*BB + b];
            const float* gi = g_gi + ((long)(n*BB + b))*(3*HH);
            float rr = 1.f/(1.f + expf(-(gi[jg]        + sr + sbv[0*4 + jgl])));
            float zz = 1.f/(1.f + expf(-(gi[HH + jg]   + sz + sbv[1*4 + jgl])));
            float nn = tanhf(gi[2*HH + jg] + rr*(sn + sbv[2*4 + jgl]));
            float hn = (1.f - zz)*nn + zz*hold;
            __stcg(hc + jg*BB + b, hn);
            g_rnn[((long)(n*BB + b))*HH + jg] = hn;
            if (n == NN-1) hid[b*HH + jg] = hn;
        }
        if (n < NN-1) gru_barrier(bk, (unsigned)(n + 2));
        float* t = hp; hp = hc; hc = t;
    }
}

// ---------------- tf32 mma GEMM (concat path, cvt at use) ----------------
__device__ __forceinline__ const float* concat_src(int m, int k) {
    if (k < HH)        return g_rnn  + (long)m*HH + k;
    if (k < 2*HH)      return g_ctx1 + (long)m*HH + (k - HH);
    if (k < 3*HH)      return g_ctx2 + (long)m*HH + (k - 2*HH);
    return g_ctx3 + (long)m*KK + (k - 3*HH);
}

__global__ __launch_bounds__(128, 2)
void k_gemm_tf32c(const float* __restrict__ W, const float* __restrict__ bias,
                  float* __restrict__ C, int Kd, int ldC) {
    __shared__ __align__(16) float As[2][128][20];
    __shared__ __align__(16) float Bs[2][128][20];
    int tid = threadIdx.x;
    int warp = tid >> 5, lane = tid & 31;
    int wm = warp & 1, wnp = warp >> 1;
    int lq = lane >> 2, lr = lane & 3;
    int m0 = blockIdx.y * 128, n0 = blockIdx.x * 128;

    float acc[4][8][4];
#pragma unroll
    for (int i = 0; i < 4; i++)
#pragma unroll
        for (int j = 0; j < 8; j++)
#pragma unroll
            for (int c = 0; c < 4; c++) acc[i][j][c] = 0.f;

    const int NK = Kd / 16;
#pragma unroll
    for (int i = 0; i < 4; i++) {
        int idx = i*128 + tid, row = idx >> 2, kc = idx & 3;
        cpa16(smem_u32(&As[0][row][kc*4]), concat_src(m0+row, kc*4));
        cpa16(smem_u32(&Bs[0][row][kc*4]), W + (long)(n0+row)*Kd + kc*4);
    }
    asm volatile("cp.async.commit_group;");

    int buf = 0;
    for (int ks = 0; ks < NK; ks++) {
        asm volatile("cp.async.wait_group 0;");
        __syncthreads();
        if (ks + 1 < NK) {
#pragma unroll
            for (int i = 0; i < 4; i++) {
                int idx = i*128 + tid, row = idx >> 2, kc = idx & 3;
                int kpos = (ks+1)*16 + kc*4;
                cpa16(smem_u32(&As[buf^1][row][kc*4]), concat_src(m0+row, kpos));
                cpa16(smem_u32(&Bs[buf^1][row][kc*4]), W + (long)(n0+row)*Kd + kpos);
            }
            asm volatile("cp.async.commit_group;");
        }
#pragma unroll
        for (int kk = 0; kk < 16; kk += 8) {
            uint32_t af[4][4], bf[8][2];
#pragma unroll
            for (int ms = 0; ms < 4; ms++) {
                int rb = wm*64 + ms*16;
                af[ms][0] = f2tf(As[buf][rb + lq    ][kk + lr    ]);
                af[ms][1] = f2tf(As[buf][rb + lq + 8][kk + lr    ]);
                af[ms][2] = f2tf(As[buf][rb + lq    ][kk + lr + 4]);
                af[ms][3] = f2tf(As[buf][rb + lq + 8][kk + lr + 4]);
            }
#pragma unroll
            for (int ns = 0; ns < 8; ns++) {
                int nb = wnp*64 + ns*8;
                bf[ns][0] = f2tf(Bs[buf][nb + lq][kk + lr    ]);
                bf[ns][1] = f2tf(Bs[buf][nb + lq][kk + lr + 4]);
            }
#pragma unroll
            for (int ms = 0; ms < 4; ms++)
#pragma unroll
                for (int ns = 0; ns < 8; ns++)
                    mma_tf32(acc[ms][ns][0], acc[ms][ns][1], acc[ms][ns][2], acc[ms][ns][3],
                             af[ms][0], af[ms][1], af[ms][2], af[ms][3],
                             bf[ns][0], bf[ns][1]);
        }
        buf ^= 1;
    }
#pragma unroll
    for (int ms = 0; ms < 4; ms++) {
        int row = m0 + wm*64 + ms*16 + lq;
#pragma unroll
        for (int ns = 0; ns < 8; ns++) {
            int col = n0 + wnp*64 + ns*8 + lr*2;
            float b0 = bias[col], b1 = bias[col+1];
            float v00 = tanhf(acc[ms][ns][0] + b0), v01 = tanhf(acc[ms][ns][1] + b1);
            float v10 = tanhf(acc[ms][ns][2] + b0), v11 = tanhf(acc[ms][ns][3] + b1);
            *(float2*)(C + (long)row*ldC + col)     = make_float2(v00, v01);
            *(float2*)(C + (long)(row+8)*ldC + col) = make_float2(v10, v11);
        }
    }
}

// split-precision tf32 GEMM for gi with fused embedding gather (A row = emb[seq[m]])
__global__ __launch_bounds__(256)
void k_gemm_tf32s(const int* __restrict__ seq, const float* __restrict__ emb,
                  const float* __restrict__ W, const float* __restrict__ bias,
                  float* __restrict__ C, int Kd, int ldC) {
    __shared__ __align__(16) float As[2][128][20];
    __shared__ __align__(16) float Bs[2][128][20];
    int tid = threadIdx.x;
    int warp = tid >> 5, lane = tid & 31;
    int wm = warp & 1, wn = warp >> 1;
    int lq = lane >> 2, lr = lane & 3;
    int m0 = blockIdx.y * 128, n0 = blockIdx.x * 128;

    // hoisted gather row pointers (each thread owns the same (row,kc) every k-step)
    const float* arow[2];
    int rowi[2], kci[2];
#pragma unroll
    for (int i = 0; i < 2; i++) {
        int idx = i*256 + tid;
        rowi[i] = idx >> 2; kci[i] = idx & 3;
        arow[i] = emb + (long)seq[m0 + rowi[i]]*Kd + kci[i]*4;
    }

    float acc[4][4][4];
#pragma unroll
    for (int i = 0; i < 4; i++)
#pragma unroll
        for (int j = 0; j < 4; j++)
#pragma unroll
            for (int c = 0; c < 4; c++) acc[i][j][c] = 0.f;

    const int NK = Kd / 16;
#pragma unroll
    for (int i = 0; i < 2; i++) {
        cpa16(smem_u32(&As[0][rowi[i]][kci[i]*4]), arow[i]);
        cpa16(smem_u32(&Bs[0][rowi[i]][kci[i]*4]), W + (long)(n0+rowi[i])*Kd + kci[i]*4);
    }
    asm volatile("cp.async.commit_group;");

    int buf = 0;
    for (int ks = 0; ks < NK; ks++) {
        asm volatile("cp.async.wait_group 0;");
        __syncthreads();
        if (ks + 1 < NK) {
#pragma unroll
            for (int i = 0; i < 2; i++) {
                cpa16(smem_u32(&As[buf^1][rowi[i]][kci[i]*4]), arow[i] + (ks+1)*16);
                cpa16(smem_u32(&Bs[buf^1][rowi[i]][kci[i]*4]),
                      W + (long)(n0+rowi[i])*Kd + (ks+1)*16 + kci[i]*4);
            }
            asm volatile("cp.async.commit_group;");
        }
#pragma unroll
        for (int kk = 0; kk < 16; kk += 8) {
            uint32_t ah[4][4], al[4][4], bh[4][2], bl[4][2];
#pragma unroll
            for (int ms = 0; ms < 4; ms++) {
                int rb = wm*64 + ms*16;
                split_tf32(As[buf][rb + lq    ][kk + lr    ], ah[ms][0], al[ms][0]);
                split_tf32(As[buf][rb + lq + 8][kk + lr    ], ah[ms][1], al[ms][1]);
                split_tf32(As[buf][rb + lq    ][kk + lr + 4], ah[ms][2], al[ms][2]);
                split_tf32(As[buf][rb + lq + 8][kk + lr + 4], ah[ms][3], al[ms][3]);
            }
#pragma unroll
            for (int ns = 0; ns < 4; ns++) {
                int nb = wn*32 + ns*8;
                split_tf32(Bs[buf][nb + lq][kk + lr    ], bh[ns][0], bl[ns][0]);
                split_tf32(Bs[buf][nb + lq][kk + lr + 4], bh[ns][1], bl[ns][1]);
            }
#pragma unroll
            for (int ms = 0; ms < 4; ms++)
#pragma unroll
                for (int ns = 0; ns < 4; ns++) {
                    mma_tf32(acc[ms][ns][0], acc[ms][ns][1], acc[ms][ns][2], acc[ms][ns][3],
                             ah[ms][0], ah[ms][1], ah[ms][2], ah[ms][3], bh[ns][0], bh[ns][1]);
                    mma_tf32(acc[ms][ns][0], acc[ms][ns][1], acc[ms][ns][2], acc[ms][ns][3],
                             ah[ms][0], ah[ms][1], ah[ms][2], ah[ms][3], bl[ns][0], bl[ns][1]);
                    mma_tf32(acc[ms][ns][0], acc[ms][ns][1], acc[ms][ns][2], acc[ms][ns][3],
                             al[ms][0], al[ms][1], al[ms][2], al[ms][3], bh[ns][0], bh[ns][1]);
                }
        }
        buf ^= 1;
    }
#pragma unroll
    for (int ms = 0; ms < 4; ms++) {
        int row = m0 + wm*64 + ms*16 + lq;
#pragma unroll
        for (int ns = 0; ns < 4; ns++) {
            int col = n0 + wn*32 + ns*8 + lr*2;
            float b0 = bias[col], b1 = bias[col+1];
            *(float2*)(C + (long)row*ldC + col)     = make_float2(acc[ms][ns][0] + b0, acc[ms][ns][1] + b1);
            *(float2*)(C + (long)(row+8)*ldC + col) = make_float2(acc[ms][ns][2] + b0, acc[ms][ns][3] + b1);
        }
    }
}

// a1/a3 dots only (c dots now computed in GRU shadow); folds flag reset
__global__ void k_ac() {
    if (blockIdx.x == 0 && threadIdx.x < GRU_BLOCKS) g_flag[threadIdx.x*32] = 0u;
    int gw = (blockIdx.x * blockDim.x + threadIdx.x) >> 5;
    int lane = threadIdx.x & 31;
    if (gw >= M2) return;
    const float4* x  = (const float4*)(g_rnn + (long)gw*HH);
    const float4* u1 = (const float4*)g_u1;
    const float4* u3 = (const float4*)g_u3;
    float s1 = 0.f, s3 = 0.f;
#pragma unroll
    for (int k = lane; k < HH/4; k += 32) {
        float4 xv = x[k], a = u1[k], b = u3[k];
        s1 += xv.x*a.x + xv.y*a.y + xv.z*a.z + xv.w*a.w;
        s3 += xv.x*b.x + xv.y*b.y + xv.z*b.z + xv.w*b.w;
    }
#pragma unroll
    for (int o = 16; o > 0; o >>= 1) {
        s1 += __shfl_xor_sync(0xffffffffu, s1, o);
        s3 += __shfl_xor_sync(0xffffffffu, s3, o);
    }
    if (lane == 0) { g_a1[gw] = s1 + g_bv[0]; g_a3[gw] = s3 + g_bv[1]; }
}

__global__ void k_softmax1(float* __restrict__ aw1) {
    int bn = blockIdx.x;
    int b = bn / NN, n = bn - b*NN;
    int t = threadIdx.x;
    float e  = tanhf(g_a1[n*BB + b] + g_c1[t*BB + b]);
    float ex = expf(e);
    __shared__ float red[8];
    __shared__ float stot;
    float s = ex;
#pragma unroll
    for (int o = 16; o > 0; o >>= 1) s += __shfl_xor_sync(0xffffffffu, s, o);
    if ((t & 31) == 0) red[t >> 5] = s;
    __syncthreads();
    if (t == 0) { float tt = 0.f; for (int i = 0; i < 8; i++) tt += red[i]; stot = tt; }
    __syncthreads();
    aw1[(long)bn*TT + t] = ex / stot;
}

__global__ void k_softmax2(float* __restrict__ aw2) {
    int gw = (blockIdx.x * blockDim.x + threadIdx.x) >> 5;
    if (gw >= BB*NN) return;
    int b = gw / NN, n = gw - b*NN;
    int s = threadIdx.x & 31;
    float e  = tanhf(g_a1[n*BB + b] + g_c2[s*BB + b]);
    float ex = expf(e);
    float tot = ex;
#pragma unroll
    for (int o = 16; o > 0; o >>= 1) tot += __shfl_xor_sync(0xffffffffu, tot, o);
    aw2[(long)gw*SS + s] = ex / tot;
}

__global__ void k_softmax3(float* __restrict__ aw3) {
    int bn = blockIdx.x * blockDim.x + threadIdx.x;
    if (bn >= BB*NN) return;
    int b = bn / NN, n = bn - b*NN;
    float ex[AA]; float tot = 0.f;
#pragma unroll
    for (int a = 0; a < AA; a++) {
        ex[a] = expf(tanhf(g_a3[n*BB + b] + g_c3[a*BB + b]));
        tot += ex[a];
    }
#pragma unroll
    for (int a = 0; a < AA; a++) aw3[(long)bn*AA + a] = ex[a] / tot;
}

// tiled ctx
__global__ void k_ctx_t(const float* __restrict__ aw, const float* __restrict__ enc,
                        float* __restrict__ dst, int L, int D) {
    int b  = blockIdx.x;
    int h0 = blockIdx.y * 64;
    int tid = threadIdx.x;
    __shared__ float AWs[64][33];
    __shared__ float Es[32][68];
    int tx = tid & 15, ty = tid >> 4;
    float acc[4][4] = {};
    for (int t0 = 0; t0 < L; t0 += 32) {
        {
            int row = tid >> 2, c0 = (tid & 3) * 8;
            const float* ap = aw + ((long)b*NN + row)*L + t0 + c0;
            float4 v0 = *(const float4*)ap;
            float4 v1 = *(const float4*)(ap + 4);
            AWs[row][c0+0]=v0.x; AWs[row][c0+1]=v0.y; AWs[row][c0+2]=v0.z; AWs[row][c0+3]=v0.w;
            AWs[row][c0+4]=v1.x; AWs[row][c0+5]=v1.y; AWs[row][c0+6]=v1.z; AWs[row][c0+7]=v1.w;
        }
        {
            int row = tid >> 3, c0 = (tid & 7) * 8;
            const float* ep = enc + (((long)(t0+row))*BB + b)*D + h0 + c0;
            float4 v0 = *(const float4*)ep;
            float4 v1 = *(const float4*)(ep + 4);
            Es[row][c0+0]=v0.x; Es[row][c0+1]=v0.y; Es[row][c0+2]=v0.z; Es[row][c0+3]=v0.w;
            Es[row][c0+4]=v1.x; Es[row][c0+5]=v1.y; Es[row][c0+6]=v1.z; Es[row][c0+7]=v1.w;
        }
        __syncthreads();
#pragma unroll
        for (int tt = 0; tt < 32; tt++) {
            float a[4], e[4];
#pragma unroll
            for (int i = 0; i < 4; i++) { a[i] = AWs[ty*4+i][tt]; e[i] = Es[tt][tx*4+i]; }
#pragma unroll
            for (int i = 0; i < 4; i++)
#pragma unroll
                for (int j = 0; j < 4; j++) acc[i][j] += a[i]*e[j];
        }
        __syncthreads();
    }
#pragma unroll
    for (int i = 0; i < 4; i++) {
        int n = ty*4 + i;
#pragma unroll
        for (int j = 0; j < 4; j++)
            dst[(((long)n)*BB + b)*D + h0 + tx*4 + j] = acc[i][j];
    }
}

// naive ctx (L=5, D=128)
__global__ void k_ctx(const float* __restrict__ aw, const float* __restrict__ enc,
                      float* __restrict__ dst, int L, int D) {
    int i = blockIdx.x * blockDim.x + threadIdx.x;
    if (i >= M2*KK) return;
    int m = i / D, h = i - m*D;
    int n = m / BB, b = m - n*BB;
    const float* awp = aw + ((long)b*NN + n)*L;
    float s = 0.f;
    for (int t = 0; t < L; t++) s += awp[t]*enc[((long)t*BB + b)*D + h];
    dst[i] = s;
}

// fused gate with embedding gather
__global__ void k_gate2(const int* __restrict__ seq, const float* __restrict__ emb,
                        const float* __restrict__ gateW, const float* __restrict__ gateb,
                        float* __restrict__ gateout) {
    int m0 = blockIdx.x * 4;
    int tid = threadIdx.x;
    __shared__ float xs[4][GIN + 12];
#pragma unroll
    for (int r = 0; r < 4; r++) {
        int m = m0 + r, b = m & 31;
        const float* er = emb + (long)seq[m]*HH;
        for (int k = tid; k < GIN; k += 256) {
            float v;
            if (k < HH)        v = er[k];
            else if (k < 2*HH) v = g_rnn[(long)m*HH + k - HH];
            else               v = g_e4[b*AN + k - 2*HH];
            xs[r][k] = v;
        }
    }
    __syncthreads();
    int w = tid >> 5, lane = tid & 31;
    for (int o = w; o < 4*AN; o += 8) {
        int r = o & 3, j = o >> 2;
        const float* wj = gateW + (long)j*GIN;
        float s = 0.f;
        for (int k = lane; k < GIN; k += 32) s += xs[r][k]*wj[k];
#pragma unroll
        for (int of = 16; of > 0; of >>= 1) s += __shfl_xor_sync(0xffffffffu, s, of);
        if (lane == 0) gateout[(long)(m0+r)*AN + j] = tanhf(s + gateb[j]);
    }
}

__global__ void k_scatter(const float* __restrict__ gate, const int* __restrict__ ids,
                          float* __restrict__ out0) {
    long i = (long)blockIdx.x * blockDim.x + threadIdx.x;
    if (i >= (long)M2*NASP) return;
    int m = (int)(i / NASP);
    int j = (int)(i - (long)m*NASP);
    if (!g_first[j]) return;
    float s = 0.f;
    int jj = j;
    while (jj >= 0) { s += gate[(long)m*AN + (jj % AN)]; jj = g_next[jj]; }
    out0[(long)m*VV + ids[j]] += s;
}

// ---------------- launcher ----------------
extern "C" void kernel_launch(void* const* d_in, const int* in_sizes, int n_in,
                              void* d_out, int out_size) {
    const int*   seq   = (const int*)  d_in[0];
    const float* lasth = (const float*)d_in[1];
    const float* enc1  = (const float*)d_in[2];
    const float* enc2  = (const float*)d_in[3];
    const float* enc3  = (const float*)d_in[4];
    const float* enc4  = (const float*)d_in[5];
    const int*   asp   = (const int*)  d_in[6];
    const float* emb   = (const float*)d_in[7];
    const float* Wih   = (const float*)d_in[8];
    const float* Whh   = (const float*)d_in[9];
    const float* bih   = (const float*)d_in[10];
    const float* bhh   = (const float*)d_in[11];
    const float* attnW = (const float*)d_in[12];
    const float* attnb = (const float*)d_in[13];
    const float* attnv = (const float*)d_in[14];
    const float* attrW = (const float*)d_in[15];
    const float* attrb = (const float*)d_in[16];
    const float* attrv = (const float*)d_in[17];
    const float* concW = (const float*)d_in[18];
    const float* concb = (const float*)d_in[19];
    const float* outW  = (const float*)d_in[20];
    const float* outb  = (const float*)d_in[21];
    const float* gateW = (const float*)d_in[22];
    const float* gateb = (const float*)d_in[23];
    const float* projW = (const float*)d_in[24];
    const float* projb = (const float*)d_in[25];
    float* out = (float*)d_out;

    const long O_HID  = (long)M2*VV;
    const long O_AW1  = O_HID + (long)BB*HH;
    const long O_AW2  = O_AW1 + (long)BB*NN*TT;
    const long O_AW3  = O_AW2 + (long)BB*NN*SS;
    const long O_GATE = O_AW3 + (long)BB*NN*AA;

    float *p_gi, *p_cout, *p_ctx1, *p_ctx2, *p_ctx3;
    uint32_t *p_wt, *p_at;
    cudaGetSymbolAddress((void**)&p_gi,   g_gi);
    cudaGetSymbolAddress((void**)&p_cout, g_cout);
    cudaGetSymbolAddress((void**)&p_ctx1, g_ctx1);
    cudaGetSymbolAddress((void**)&p_ctx2, g_ctx2);
    cudaGetSymbolAddress((void**)&p_ctx3, g_ctx3);
    cudaGetSymbolAddress((void**)&p_wt,   g_wt);
    cudaGetSymbolAddress((void**)&p_at,   g_at);

    const int GRU_SMEM = (6144 + 16384 + 3072 + 16) * 4;   // ~100KB
    cudaFuncSetAttribute(k_gru_all, cudaFuncAttributeMaxDynamicSharedMemorySize, GRU_SMEM);

    // 1) gi = emb[seq] @ Wih^T + bih (split-tf32, fused embedding gather)
    k_gemm_tf32s<<<dim3((3*HH)/128, M2/128), 256>>>(seq, emb, Wih, bih, p_gi, HH, 3*HH);

    // 2) mega kernel: GRU (128 blocks) + shadow work (uvec, c-dots, pack_w, e4, chain) on 20 SMs
    k_gru_all<<<GRU_BLOCKS + SIDE_BLOCKS, 512, GRU_SMEM>>>(
        lasth, Whh, bhh, out + O_HID,
        outW, attnW, attnv, attnb, attrW, attrv, attrb, enc4, projW, projb, asp,
        enc1, enc2, enc3);

    // 3) a1/a3 dots (+ flag reset)
    k_ac<<<(M2*32 + 255)/256, 256>>>();

    // 4) softmaxes
    k_softmax1<<<BB*NN, TT>>>(out + O_AW1);
    k_softmax2<<<(BB*NN*32 + 255)/256, 256>>>(out + O_AW2);
    k_softmax3<<<(BB*NN + 255)/256, 256>>>(out + O_AW3);

    // 5) contexts
    k_ctx_t<<<dim3(BB, HH/64), 256>>>(out + O_AW1, enc1, p_ctx1, TT, HH);
    k_ctx_t<<<dim3(BB, HH/64), 256>>>(out + O_AW2, enc2, p_ctx2, SS, HH);
    k_ctx  <<<(M2*KK + 255)/256, 256>>>(out + O_AW3, enc3, p_ctx3, AA, KK);

    // 6) concat GEMM (tf32, tanh) -> A pack -> packed tf32 big GEMM
    k_gemm_tf32c<<<dim3(HH/128, M2/128), 128>>>(concW, concb, p_cout, CIN, HH);
    k_pack_a<<<(int)(((long)(M2/128)*64*8*32 + 255)/256), 256>>>(p_cout);
    k_gemm_tf32p<<<dim3(M2/128, VV/128), 128>>>((const uint4*)p_at, (const uint4*)p_wt, outb, out);

    // 7) gate path (emb gathered directly)
    k_gate2<<<M2/4, 256>>>(seq, emb, gateW, gateb, out + O_GATE);

    // 8) deterministic scatter-add
    k_scatter<<<(int)(((long)M2*NASP + 255)/256), 256>>>(out + O_GATE, asp, out);
}

// round 15
// speedup vs baseline: 1.0673x; 1.0673x over previous
#include <cuda_runtime.h>
#include <cuda_bf16.h>
#include <math.h>
#include <stdint.h>

#define NN 64
#define BB 32
#define HH 512
#define KK 128
#define VV 32000
#define TT 256
#define SS 32
#define AA 5
#define AN 20
#define M2 (NN*BB)          // 2048 rows
#define CIN (3*HH+KK)       // 1664
#define GIN (2*HH+AN)       // 1044
#define NASP 2000
#define GRU_BLOCKS 128
#define SIDE_BLOCKS 20
#define UCOLS (2*HH + HH + KK)   // 1664 projected columns

// ---------------- scratch (static device globals; no runtime alloc) ----------------
__device__ __align__(16) float g_emb[M2*HH];
__device__ __align__(16) float g_gi[M2*3*HH];
__device__ __align__(16) float g_hA[HH*BB];
__device__ __align__(16) float g_hB[HH*BB];
__device__ __align__(16) float g_rnn[M2*HH];
__device__ __align__(16) float g_u1[HH];
__device__ __align__(16) float g_u1e[HH];
__device__ __align__(16) float g_u3[HH];
__device__ __align__(16) float g_u3e[KK];
__device__ float g_bv[2];
__device__ float g_a1[M2], g_a3[M2];
__device__ float g_c1[TT*BB], g_c2[SS*BB], g_c3[AA*BB];
__device__ __align__(16) float g_ctx1[M2*HH];
__device__ __align__(16) float g_ctx2[M2*HH];
__device__ __align__(16) float g_ctx3[M2*KK];
__device__ __align__(16) float g_cout[M2*HH];
__device__ __align__(16) uint32_t g_wt[VV*HH];      // 65.5 MB pre-rounded, fragment-packed W
__device__ __align__(16) uint32_t g_at[M2*HH];      // 4 MB fragment-packed A
__device__ float g_e4[BB*AN];
__device__ int g_first[NASP], g_next[NASP];
__device__ __align__(128) unsigned g_flag[GRU_BLOCKS*32] = {0};

// ---------------- contention-free flag barrier (GRU blocks only; monotonic) ----------------
__device__ __forceinline__ void gru_barrier(int bk, unsigned step) {
    __syncthreads();
    if (threadIdx.x == 0) {
        asm volatile("st.release.gpu.global.u32 [%0], %1;"
                     :: "l"(&g_flag[bk*32]), "r"(step) : "memory");
    }
    if (threadIdx.x < GRU_BLOCKS) {
        unsigned v;
        do {
            asm volatile("ld.acquire.gpu.global.u32 %0, [%1];"
                         : "=r"(v) : "l"(&g_flag[threadIdx.x*32]) : "memory");
        } while (v < step);
    }
    __syncthreads();
}

// ---------------- helpers ----------------
__device__ __forceinline__ uint32_t smem_u32(const void* p) {
    uint32_t a;
    asm("{ .reg .u64 t; cvta.to.shared.u64 t, %1; cvt.u32.u64 %0, t; }" : "=r"(a) : "l"(p));
    return a;
}
__device__ __forceinline__ uint32_t f2tf(float x) {
    uint32_t u; asm("cvt.rna.tf32.f32 %0, %1;" : "=r"(u) : "f"(x)); return u;
}
__device__ __forceinline__ void split_tf32(float x, uint32_t& hi, uint32_t& lo) {
    hi = f2tf(x);
    float r = x - __uint_as_float(hi);
    lo = f2tf(r);
}
__device__ __forceinline__ void mma_tf32(float& c0, float& c1, float& c2, float& c3,
                                         uint32_t a0, uint32_t a1, uint32_t a2, uint32_t a3,
                                         uint32_t b0, uint32_t b1) {
    asm volatile("mma.sync.aligned.m16n8k8.row.col.f32.tf32.tf32.f32 "
                 "{%0,%1,%2,%3},{%4,%5,%6,%7},{%8,%9},{%0,%1,%2,%3};"
                 : "+f"(c0), "+f"(c1), "+f"(c2), "+f"(c3)
                 : "r"(a0), "r"(a1), "r"(a2), "r"(a3), "r"(b0), "r"(b1));
}
__device__ __forceinline__ void cpa16(uint32_t saddr, const void* gaddr) {
    asm volatile("cp.async.cg.shared.global [%0], [%1], 16;" :: "r"(saddr), "l"(gaddr));
}

// ---------------- kernels ----------------

__global__ void k_embed(const int* __restrict__ seq, const float* __restrict__ emb) {
    int i = blockIdx.x * blockDim.x + threadIdx.x;
    if (i < M2*HH) {
        int m = i / HH, h = i - m*HH;
        g_emb[i] = emb[(long)seq[m]*HH + h];
    }
}

// A pack for the big GEMM
__global__ void k_pack_a(const float* __restrict__ A) {
    long i = (long)blockIdx.x * 256 + threadIdx.x;
    if (i >= (long)(M2/128)*64*8*32) return;
    int lane = (int)(i & 31), mf = (int)((i >> 5) & 7), s = (int)((i >> 8) & 63);
    long mb = i >> 14;
    int lq = lane >> 2, lr = lane & 3;
    int k = s*8 + lr;
    long me = mb*128 + mf*16 + lq;
    uint4 v;
    v.x = f2tf(A[me*HH + k]);
    v.y = f2tf(A[(me+8)*HH + k]);
    v.z = f2tf(A[me*HH + k + 4]);
    v.w = f2tf(A[(me+8)*HH + k + 4]);
    ((uint4*)g_at)[i] = v;
}

// ---------------- packed tf32 GEMM: C[M2,VV] = A[M2,HH] * W[VV,HH]^T + bias ----------------
__global__ __launch_bounds__(128, 2)
void k_gemm_tf32p(const uint4* __restrict__ At, const uint4* __restrict__ Wt,
                  const float* __restrict__ bias, float* __restrict__ C) {
    __shared__ __align__(16) uint4 As[2][512];
    __shared__ __align__(16) uint4 Bs[2][512];
    int tid = threadIdx.x;
    int warp = tid >> 5, lane = tid & 31;
    int wm = warp & 1, wnp = warp >> 1;
    int lq = lane >> 2, lr = lane & 3;
    int m0 = blockIdx.x * 128, n0 = blockIdx.y * 128;
    const uint4* Ab = At + (long)blockIdx.x * 16384;
    const uint4* Bb = Wt + (long)blockIdx.y * 16384;

    float acc[4][8][4];
#pragma unroll
    for (int i = 0; i < 4; i++)
#pragma unroll
        for (int j = 0; j < 8; j++)
#pragma unroll
            for (int c = 0; c < 4; c++) acc[i][j][c] = 0.f;

#pragma unroll
    for (int i = 0; i < 4; i++) {
        cpa16(smem_u32(&As[0][i*128 + tid]), Ab + i*128 + tid);
        cpa16(smem_u32(&Bs[0][i*128 + tid]), Bb + i*128 + tid);
    }
    asm volatile("cp.async.commit_group;");

    int buf = 0;
    const int NK = HH / 16;
    for (int c = 0; c < NK; c++) {
        asm volatile("cp.async.wait_group 0;" ::: "memory");
        __syncthreads();
        if (c + 1 < NK) {
            const uint4* an = Ab + (c+1)*512;
            const uint4* bn = Bb + (c+1)*512;
#pragma unroll
            for (int i = 0; i < 4; i++) {
                cpa16(smem_u32(&As[buf^1][i*128 + tid]), an + i*128 + tid);
                cpa16(smem_u32(&Bs[buf^1][i*128 + tid]), bn + i*128 + tid);
            }
            asm volatile("cp.async.commit_group;");
        }
#pragma unroll
        for (int kk = 0; kk < 2; kk++) {
            uint4 av[4], bv[4];
#pragma unroll
            for (int ms = 0; ms < 4; ms++)
                av[ms] = As[buf][kk*256 + (wm*4 + ms)*32 + lane];
#pragma unroll
            for (int p = 0; p < 4; p++)
                bv[p] = Bs[buf][kk*256 + (wnp*4 + p)*32 + lane];
#pragma unroll
            for (int ms = 0; ms < 4; ms++)
#pragma unroll
                for (int p = 0; p < 4; p++) {
                    mma_tf32(acc[ms][2*p][0], acc[ms][2*p][1], acc[ms][2*p][2], acc[ms][2*p][3],
                             av[ms].x, av[ms].y, av[ms].z, av[ms].w, bv[p].x, bv[p].y);
                    mma_tf32(acc[ms][2*p+1][0], acc[ms][2*p+1][1], acc[ms][2*p+1][2], acc[ms][2*p+1][3],
                             av[ms].x, av[ms].y, av[ms].z, av[ms].w, bv[p].z, bv[p].w);
                }
        }
        buf ^= 1;
    }
#pragma unroll
    for (int ms = 0; ms < 4; ms++) {
        int row = m0 + wm*64 + ms*16 + lq;
#pragma unroll
        for (int ns = 0; ns < 8; ns++) {
            int col = n0 + wnp*64 + ns*8 + lr*2;
            float b0 = bias[col], b1 = bias[col+1];
            *(float2*)(C + (long)row*VV + col)     = make_float2(acc[ms][ns][0] + b0, acc[ms][ns][1] + b1);
            *(float2*)(C + (long)(row+8)*VV + col) = make_float2(acc[ms][ns][2] + b0, acc[ms][ns][3] + b1);
        }
    }
}

// ---------------- mega kernel: persistent GRU (0..127) + side work (128..147) ----------------
__global__ __launch_bounds__(512, 1)
void k_gru_all(const float* __restrict__ lasth, const float* __restrict__ Whh,
               const float* __restrict__ bhh, float* __restrict__ hid,
               const float* __restrict__ outW,
               const float* __restrict__ attnW, const float* __restrict__ attnv,
               const float* __restrict__ attnb, const float* __restrict__ attrW,
               const float* __restrict__ attrv, const float* __restrict__ attrb,
               const float* __restrict__ enc4, const float* __restrict__ projW,
               const float* __restrict__ projb, const int* __restrict__ asp) {
    extern __shared__ __align__(16) float dsm[];
    int tid = threadIdx.x, bk = blockIdx.x;

    if (bk >= GRU_BLOCKS) {
        // ===================== side work on 20 spare SMs =====================
        int sb = bk - GRU_BLOCKS;
        // (a) W fragment pack (grid-strided over side blocks)
        const long TOTW = (long)(VV/128)*64*8*32;
        for (long i = (long)sb*512 + tid; i < TOTW; i += (long)SIDE_BLOCKS*512) {
            int lane = (int)(i & 31), fp = (int)((i >> 5) & 7), s = (int)((i >> 8) & 63);
            long nb = i >> 14;
            int lq = lane >> 2, lr = lane & 3;
            int k = s*8 + lr;
            long ne = nb*128 + fp*16 + lq;
            uint4 v;
            v.x = f2tf(outW[ne*HH + k]);
            v.y = f2tf(outW[ne*HH + k + 4]);
            v.z = f2tf(outW[(ne+8)*HH + k]);
            v.w = f2tf(outW[(ne+8)*HH + k + 4]);
            ((uint4*)g_wt)[i] = v;
        }
        // (b) uvec: full-column warp dots
        {
            int gw2 = sb*16 + (tid >> 5);
            int lane = tid & 31;
            for (int t = gw2; t < UCOLS + 2; t += SIDE_BLOCKS*16) {
                float s = 0.f;
                if (t < UCOLS) {
                    const float* W; const float* v; int ld; int c;
                    if (t < 2*HH) { W = attnW; v = attnv; ld = 2*HH;    c = t; }
                    else          { W = attrW; v = attrv; ld = HH + KK; c = t - 2*HH; }
                    for (int h = lane; h < HH; h += 32) s += W[(long)h*ld + c]*v[h];
#pragma unroll
                    for (int o = 16; o > 0; o >>= 1) s += __shfl_xor_sync(0xffffffffu, s, o);
                    if (lane == 0) {
                        if (t < HH)            g_u1[t] = s;
                        else if (t < 2*HH)     g_u1e[t - HH] = s;
                        else if (t < 3*HH)     g_u3[t - 2*HH] = s;
                        else                   g_u3e[t - 3*HH] = s;
                    }
                } else {
                    int w = t - UCOLS;
                    const float* bp = w ? attrb : attnb;
                    const float* vp = w ? attrv : attnv;
                    for (int h = lane; h < HH; h += 32) s += bp[h]*vp[h];
#pragma unroll
                    for (int o = 16; o > 0; o >>= 1) s += __shfl_xor_sync(0xffffffffu, s, o);
                    if (lane == 0) g_bv[w] = s;
                }
            }
        }
        // (c) e4 projection (block sb==0)
        if (sb == 0) {
            for (int i = tid; i < BB*AN; i += 512) {
                int b = i / AN, j = i - b*AN;
                float s = projb[j];
                for (int k = 0; k < AN; k++) s += enc4[(0*BB + b)*AN + k]*projW[j*2*AN + k];
                for (int k = 0; k < AN; k++) s += enc4[(1*BB + b)*AN + k]*projW[j*2*AN + AN + k];
                g_e4[i] = s;
            }
        }
        // (d) duplicate-chain (block sb==1), smem lockstep scan
        if (sb == 1) {
            int* sid = (int*)dsm;
            for (int k = tid; k < NASP; k += 512) sid[k] = asp[k];
            __syncthreads();
            for (int j = tid; j < NASP; j += 512) {
                int v = sid[j];
                int fst = 1, nxt = -1;
                for (int j2 = 0; j2 < NASP; j2++) {
                    int w = sid[j2];
                    if (w == v) {
                        if (j2 < j) fst = 0;
                        else if (j2 > j && nxt < 0) nxt = j2;
                    }
                }
                g_first[j] = fst;
                g_next[j]  = nxt;
            }
        }
        return;
    }

    // ===================== persistent GRU =====================
    float* sw   = dsm;                    // 6144
    float* sh   = dsm + 6144;             // 16384
    float* part = dsm + 6144 + 16384;     // 3072
    float* sbv  = part + 3072;            // 12

    int b  = tid & 31;
    int ju = (tid >> 5) & 1;
    int kq = tid >> 6;

    for (int r = 0; r < 12; r++) {
        int g = r / 4, j = r % 4;
        int rowi = g*HH + bk*4 + j;
        for (int k = tid; k < HH; k += 512) sw[(g*4 + j)*HH + k] = Whh[(long)rowi*HH + k];
    }
    if (tid < 12) sbv[tid] = bhh[(tid/4)*HH + bk*4 + (tid%4)];

    if (tid < 128) {
        int idx = bk*128 + tid;
        int k = idx >> 5, bb = idx & 31;
        __stcg(&g_hA[idx], lasth[bb*HH + k]);
    }
    gru_barrier(bk, 1u);

    float* hp = g_hA;
    float* hc = g_hB;
    int u0 = ju*2;
    const float* wr0 = sw + (0*4 + u0    )*HH;
    const float* wr1 = sw + (0*4 + u0 + 1)*HH;
    const float* wz0 = sw + (1*4 + u0    )*HH;
    const float* wz1 = sw + (1*4 + u0 + 1)*HH;
    const float* wn0 = sw + (2*4 + u0    )*HH;
    const float* wn1 = sw + (2*4 + u0 + 1)*HH;
    int k0 = kq * 64;

    for (int n = 0; n < NN; n++) {
#pragma unroll
        for (int i = 0; i < 8; i++) {
            int f = tid + i*512;
            float4 v = __ldcg((const float4*)hp + f);
            *(float4*)(sh + 4*f) = v;
        }
        __syncthreads();

        float sr0 = 0.f, sz0 = 0.f, sn0 = 0.f;
        float sr1 = 0.f, sz1 = 0.f, sn1 = 0.f;
#pragma unroll 4
        for (int k = k0; k < k0 + 64; k += 4) {
            float h0 = sh[(k+0)*BB + b];
            float h1 = sh[(k+1)*BB + b];
            float h2 = sh[(k+2)*BB + b];
            float h3 = sh[(k+3)*BB + b];
            float4 a;
            a = *(const float4*)(wr0 + k); sr0 += a.x*h0 + a.y*h1 + a.z*h2 + a.w*h3;
            a = *(const float4*)(wz0 + k); sz0 += a.x*h0 + a.y*h1 + a.z*h2 + a.w*h3;
            a = *(const float4*)(wn0 + k); sn0 += a.x*h0 + a.y*h1 + a.z*h2 + a.w*h3;
            a = *(const float4*)(wr1 + k); sr1 += a.x*h0 + a.y*h1 + a.z*h2 + a.w*h3;
            a = *(const float4*)(wz1 + k); sz1 += a.x*h0 + a.y*h1 + a.z*h2 + a.w*h3;
            a = *(const float4*)(wn1 + k); sn1 += a.x*h0 + a.y*h1 + a.z*h2 + a.w*h3;
        }
        part[((0*4 + u0    )*8 + kq)*32 + b] = sr0;
        part[((1*4 + u0    )*8 + kq)*32 + b] = sz0;
        part[((2*4 + u0    )*8 + kq)*32 + b] = sn0;
        part[((0*4 + u0 + 1)*8 + kq)*32 + b] = sr1;
        part[((1*4 + u0 + 1)*8 + kq)*32 + b] = sz1;
        part[((2*4 + u0 + 1)*8 + kq)*32 + b] = sn1;
        __syncthreads();

        if (kq < 2) {
            int jgl = u0 + kq;
            int jg  = bk*4 + jgl;
            float sr = 0.f, sz = 0.f, sn = 0.f;
#pragma unroll
            for (int q = 0; q < 8; q++) {
                sr += part[((0*4 + jgl)*8 + q)*32 + b];
                sz += part[((1*4 + jgl)*8 + q)*32 + b];
                sn += part[((2*4 + jgl)*8 + q)*32 + b];
            }
            float hold = sh[jg*BB + b];
            const float* gi = g_gi + ((long)(n*BB + b))*(3*HH);
            float rr = 1.f/(1.f + expf(-(gi[jg]        + sr + sbv[0*4 + jgl])));
            float zz = 1.f/(1.f + expf(-(gi[HH + jg]   + sz + sbv[1*4 + jgl])));
            float nn = tanhf(gi[2*HH + jg] + rr*(sn + sbv[2*4 + jgl]));
            float hn = (1.f - zz)*nn + zz*hold;
            __stcg(hc + jg*BB + b, hn);
            g_rnn[((long)(n*BB + b))*HH + jg] = hn;
            if (n == NN-1) hid[b*HH + jg] = hn;
        }
        if (n < NN-1) gru_barrier(bk, (unsigned)(n + 2));
        float* t = hp; hp = hc; hc = t;
    }
}

// ---------------- tf32 mma GEMM (concat path, cvt at use) ----------------
__device__ __forceinline__ const float* concat_src(int m, int k) {
    if (k < HH)        return g_rnn  + (long)m*HH + k;
    if (k < 2*HH)      return g_ctx1 + (long)m*HH + (k - HH);
    if (k < 3*HH)      return g_ctx2 + (long)m*HH + (k - 2*HH);
    return g_ctx3 + (long)m*KK + (k - 3*HH);
}

template<int ASRC>
__global__ __launch_bounds__(128, 2)
void k_gemm_tf32(const float* __restrict__ A, const float* __restrict__ W,
                 const float* __restrict__ bias, float* __restrict__ C,
                 int Kd, int ldC, int act) {
    __shared__ __align__(16) float As[2][128][20];
    __shared__ __align__(16) float Bs[2][128][20];
    int tid = threadIdx.x;
    int warp = tid >> 5, lane = tid & 31;
    int wm = warp & 1, wnp = warp >> 1;
    int lq = lane >> 2, lr = lane & 3;
    int m0 = blockIdx.y * 128, n0 = blockIdx.x * 128;

    float acc[4][8][4];
#pragma unroll
    for (int i = 0; i < 4; i++)
#pragma unroll
        for (int j = 0; j < 8; j++)
#pragma unroll
            for (int c = 0; c < 4; c++) acc[i][j][c] = 0.f;

    const int NK = Kd / 16;
#pragma unroll
    for (int i = 0; i < 4; i++) {
        int idx = i*128 + tid, row = idx >> 2, kc = idx & 3;
        const float* asrc = ASRC ? concat_src(m0+row, kc*4)
                                 : A + (long)(m0+row)*Kd + kc*4;
        cpa16(smem_u32(&As[0][row][kc*4]), asrc);
        cpa16(smem_u32(&Bs[0][row][kc*4]), W + (long)(n0+row)*Kd + kc*4);
    }
    asm volatile("cp.async.commit_group;");

    int buf = 0;
    for (int ks = 0; ks < NK; ks++) {
        asm volatile("cp.async.wait_group 0;");
        __syncthreads();
        if (ks + 1 < NK) {
#pragma unroll
            for (int i = 0; i < 4; i++) {
                int idx = i*128 + tid, row = idx >> 2, kc = idx & 3;
                int kpos = (ks+1)*16 + kc*4;
                const float* asrc = ASRC ? concat_src(m0+row, kpos)
                                         : A + (long)(m0+row)*Kd + kpos;
                cpa16(smem_u32(&As[buf^1][row][kc*4]), asrc);
                cpa16(smem_u32(&Bs[buf^1][row][kc*4]), W + (long)(n0+row)*Kd + kpos);
            }
            asm volatile("cp.async.commit_group;");
        }
#pragma unroll
        for (int kk = 0; kk < 16; kk += 8) {
            uint32_t af[4][4], bf[8][2];
#pragma unroll
            for (int ms = 0; ms < 4; ms++) {
                int rb = wm*64 + ms*16;
                af[ms][0] = f2tf(As[buf][rb + lq    ][kk + lr    ]);
                af[ms][1] = f2tf(As[buf][rb + lq + 8][kk + lr    ]);
                af[ms][2] = f2tf(As[buf][rb + lq    ][kk + lr + 4]);
                af[ms][3] = f2tf(As[buf][rb + lq + 8][kk + lr + 4]);
            }
#pragma unroll
            for (int ns = 0; ns < 8; ns++) {
                int nb = wnp*64 + ns*8;
                bf[ns][0] = f2tf(Bs[buf][nb + lq][kk + lr    ]);
                bf[ns][1] = f2tf(Bs[buf][nb + lq][kk + lr + 4]);
            }
#pragma unroll
            for (int ms = 0; ms < 4; ms++)
#pragma unroll
                for (int ns = 0; ns < 8; ns++)
                    mma_tf32(acc[ms][ns][0], acc[ms][ns][1], acc[ms][ns][2], acc[ms][ns][3],
                             af[ms][0], af[ms][1], af[ms][2], af[ms][3],
                             bf[ns][0], bf[ns][1]);
        }
        buf ^= 1;
    }
#pragma unroll
    for (int ms = 0; ms < 4; ms++) {
        int row = m0 + wm*64 + ms*16 + lq;
#pragma unroll
        for (int ns = 0; ns < 8; ns++) {
            int col = n0 + wnp*64 + ns*8 + lr*2;
            float b0 = bias[col], b1 = bias[col+1];
            float v00 = acc[ms][ns][0] + b0, v01 = acc[ms][ns][1] + b1;
            float v10 = acc[ms][ns][2] + b0, v11 = acc[ms][ns][3] + b1;
            if (act) { v00 = tanhf(v00); v01 = tanhf(v01); v10 = tanhf(v10); v11 = tanhf(v11); }
            *(float2*)(C + (long)row*ldC + col)     = make_float2(v00, v01);
            *(float2*)(C + (long)(row+8)*ldC + col) = make_float2(v10, v11);
        }
    }
}

// split-precision tf32 GEMM (fp32-accurate) for gi
__global__ __launch_bounds__(256)
void k_gemm_tf32s(const float* __restrict__ A, const float* __restrict__ W,
                  const float* __restrict__ bias, float* __restrict__ C,
                  int Kd, int ldC) {
    __shared__ __align__(16) float As[2][128][20];
    __shared__ __align__(16) float Bs[2][128][20];
    int tid = threadIdx.x;
    int warp = tid >> 5, lane = tid & 31;
    int wm = warp & 1, wn = warp >> 1;
    int lq = lane >> 2, lr = lane & 3;
    int m0 = blockIdx.y * 128, n0 = blockIdx.x * 128;

    float acc[4][4][4];
#pragma unroll
    for (int i = 0; i < 4; i++)
#pragma unroll
        for (int j = 0; j < 4; j++)
#pragma unroll
            for (int c = 0; c < 4; c++) acc[i][j][c] = 0.f;

    const int NK = Kd / 16;
#pragma unroll
    for (int i = 0; i < 2; i++) {
        int idx = i*256 + tid, row = idx >> 2, kc = idx & 3;
        cpa16(smem_u32(&As[0][row][kc*4]), A + (long)(m0+row)*Kd + kc*4);
        cpa16(smem_u32(&Bs[0][row][kc*4]), W + (long)(n0+row)*Kd + kc*4);
    }
    asm volatile("cp.async.commit_group;");

    int buf = 0;
    for (int ks = 0; ks < NK; ks++) {
        asm volatile("cp.async.wait_group 0;");
        __syncthreads();
        if (ks + 1 < NK) {
#pragma unroll
            for (int i = 0; i < 2; i++) {
                int idx = i*256 + tid, row = idx >> 2, kc = idx & 3;
                int kpos = (ks+1)*16 + kc*4;
                cpa16(smem_u32(&As[buf^1][row][kc*4]), A + (long)(m0+row)*Kd + kpos);
                cpa16(smem_u32(&Bs[buf^1][row][kc*4]), W + (long)(n0+row)*Kd + kpos);
            }
            asm volatile("cp.async.commit_group;");
        }
#pragma unroll
        for (int kk = 0; kk < 16; kk += 8) {
            uint32_t ah[4][4], al[4][4], bh[4][2], bl[4][2];
#pragma unroll
            for (int ms = 0; ms < 4; ms++) {
                int rb = wm*64 + ms*16;
                split_tf32(As[buf][rb + lq    ][kk + lr    ], ah[ms][0], al[ms][0]);
                split_tf32(As[buf][rb + lq + 8][kk + lr    ], ah[ms][1], al[ms][1]);
                split_tf32(As[buf][rb + lq    ][kk + lr + 4], ah[ms][2], al[ms][2]);
                split_tf32(As[buf][rb + lq + 8][kk + lr + 4], ah[ms][3], al[ms][3]);
            }
#pragma unroll
            for (int ns = 0; ns < 4; ns++) {
                int nb = wn*32 + ns*8;
                split_tf32(Bs[buf][nb + lq][kk + lr    ], bh[ns][0], bl[ns][0]);
                split_tf32(Bs[buf][nb + lq][kk + lr + 4], bh[ns][1], bl[ns][1]);
            }
#pragma unroll
            for (int ms = 0; ms < 4; ms++)
#pragma unroll
                for (int ns = 0; ns < 4; ns++) {
                    mma_tf32(acc[ms][ns][0], acc[ms][ns][1], acc[ms][ns][2], acc[ms][ns][3],
                             ah[ms][0], ah[ms][1], ah[ms][2], ah[ms][3], bh[ns][0], bh[ns][1]);
                    mma_tf32(acc[ms][ns][0], acc[ms][ns][1], acc[ms][ns][2], acc[ms][ns][3],
                             ah[ms][0], ah[ms][1], ah[ms][2], ah[ms][3], bl[ns][0], bl[ns][1]);
                    mma_tf32(acc[ms][ns][0], acc[ms][ns][1], acc[ms][ns][2], acc[ms][ns][3],
                             al[ms][0], al[ms][1], al[ms][2], al[ms][3], bh[ns][0], bh[ns][1]);
                }
        }
        buf ^= 1;
    }
#pragma unroll
    for (int ms = 0; ms < 4; ms++) {
        int row = m0 + wm*64 + ms*16 + lq;
#pragma unroll
        for (int ns = 0; ns < 4; ns++) {
            int col = n0 + wn*32 + ns*8 + lr*2;
            float b0 = bias[col], b1 = bias[col+1];
            *(float2*)(C + (long)row*ldC + col)     = make_float2(acc[ms][ns][0] + b0, acc[ms][ns][1] + b1);
            *(float2*)(C + (long)(row+8)*ldC + col) = make_float2(acc[ms][ns][2] + b0, acc[ms][ns][3] + b1);
        }
    }
}

// all scalar attention dot products (a-dots + c-dots); block 0 also resets GRU flags
__global__ void k_ac(const float* __restrict__ enc1, const float* __restrict__ enc2,
                     const float* __restrict__ enc3) {
    if (blockIdx.x == 0 && threadIdx.x < GRU_BLOCKS) g_flag[threadIdx.x*32] = 0u;
    int gw = (blockIdx.x * blockDim.x + threadIdx.x) >> 5;
    int lane = threadIdx.x & 31;
    const int E_A = M2, E_C1 = E_A + TT*BB, E_C2 = E_C1 + SS*BB, E_C3 = E_C2 + AA*BB;
    if (gw >= E_C3) return;
    if (gw < E_A) {
        const float4* x = (const float4*)(g_rnn + (long)gw*HH);
        const float4* u1 = (const float4*)g_u1;
        const float4* u3 = (const float4*)g_u3;
        float s1 = 0.f, s3 = 0.f;
#pragma unroll
        for (int k = lane; k < HH/4; k += 32) {
            float4 xv = x[k], a = u1[k], b = u3[k];
            s1 += xv.x*a.x + xv.y*a.y + xv.z*a.z + xv.w*a.w;
            s3 += xv.x*b.x + xv.y*b.y + xv.z*b.z + xv.w*b.w;
        }
#pragma unroll
        for (int o = 16; o > 0; o >>= 1) {
            s1 += __shfl_xor_sync(0xffffffffu, s1, o);
            s3 += __shfl_xor_sync(0xffffffffu, s3, o);
        }
        if (lane == 0) { g_a1[gw] = s1 + g_bv[0]; g_a3[gw] = s3 + g_bv[1]; }
        return;
    }
    const float* x; const float* u; float* dst; int len = HH;
    if (gw < E_C1)      { int m = gw - E_A;   x = enc1 + (long)m*HH; u = g_u1e; dst = g_c1 + m; }
    else if (gw < E_C2) { int m = gw - E_C1;  x = enc2 + (long)m*HH; u = g_u1e; dst = g_c2 + m; }
    else                { int m = gw - E_C2;  x = enc3 + (long)m*KK; u = g_u3e; dst = g_c3 + m; len = KK; }
    const float4* x4 = (const float4*)x;
    const float4* u4 = (const float4*)u;
    float s = 0.f;
    for (int k = lane; k < len/4; k += 32) {
        float4 xv = x4[k], uv = u4[k];
        s += xv.x*uv.x + xv.y*uv.y + xv.z*uv.z + xv.w*uv.w;
    }
#pragma unroll
    for (int o = 16; o > 0; o >>= 1) s += __shfl_xor_sync(0xffffffffu, s, o);
    if (lane == 0) *dst = s;
}

// merged softmaxes: blocks [0,2048) = aw1; [2048,2304) = aw2; [2304,2312) = aw3
__global__ void k_softmax_all(float* __restrict__ aw1, float* __restrict__ aw2,
                              float* __restrict__ aw3) {
    int blk = blockIdx.x;
    int tid = threadIdx.x;
    if (blk < BB*NN) {
        int bn = blk;
        int b = bn / NN, n = bn - b*NN;
        float e  = tanhf(g_a1[n*BB + b] + g_c1[tid*BB + b]);
        float ex = expf(e);
        __shared__ float red[8];
        __shared__ float stot;
        float s = ex;
#pragma unroll
        for (int o = 16; o > 0; o >>= 1) s += __shfl_xor_sync(0xffffffffu, s, o);
        if ((tid & 31) == 0) red[tid >> 5] = s;
        __syncthreads();
        if (tid == 0) { float tt = 0.f; for (int i = 0; i < 8; i++) tt += red[i]; stot = tt; }
        __syncthreads();
        aw1[(long)bn*TT + tid] = ex / stot;
    } else if (blk < BB*NN + 256) {
        int gw = (blk - BB*NN)*8 + (tid >> 5);
        int b = gw / NN, n = gw - b*NN;
        int s2 = tid & 31;
        float e  = tanhf(g_a1[n*BB + b] + g_c2[s2*BB + b]);
        float ex = expf(e);
        float tot = ex;
#pragma unroll
        for (int o = 16; o > 0; o >>= 1) tot += __shfl_xor_sync(0xffffffffu, tot, o);
        aw2[(long)gw*SS + s2] = ex / tot;
    } else {
        int bn = (blk - BB*NN - 256)*256 + tid;
        if (bn >= BB*NN) return;
        int b = bn / NN, n = bn - b*NN;
        float ex[AA]; float tot = 0.f;
#pragma unroll
        for (int a = 0; a < AA; a++) {
            ex[a] = expf(tanhf(g_a3[n*BB + b] + g_c3[a*BB + b]));
            tot += ex[a];
        }
#pragma unroll
        for (int a = 0; a < AA; a++) aw3[(long)bn*AA + a] = ex[a] / tot;
    }
}

// tiled ctx
__global__ void k_ctx_t(const float* __restrict__ aw, const float* __restrict__ enc,
                        float* __restrict__ dst, int L, int D) {
    int b  = blockIdx.x;
    int h0 = blockIdx.y * 64;
    int tid = threadIdx.x;
    __shared__ float AWs[64][33];
    __shared__ float Es[32][68];
    int tx = tid & 15, ty = tid >> 4;
    float acc[4][4] = {};
    for (int t0 = 0; t0 < L; t0 += 32) {
        {
            int row = tid >> 2, c0 = (tid & 3) * 8;
            const float* ap = aw + ((long)b*NN + row)*L + t0 + c0;
            float4 v0 = *(const float4*)ap;
            float4 v1 = *(const float4*)(ap + 4);
            AWs[row][c0+0]=v0.x; AWs[row][c0+1]=v0.y; AWs[row][c0+2]=v0.z; AWs[row][c0+3]=v0.w;
            AWs[row][c0+4]=v1.x; AWs[row][c0+5]=v1.y; AWs[row][c0+6]=v1.z; AWs[row][c0+7]=v1.w;
        }
        {
            int row = tid >> 3, c0 = (tid & 7) * 8;
            const float* ep = enc + (((long)(t0+row))*BB + b)*D + h0 + c0;
            float4 v0 = *(const float4*)ep;
            float4 v1 = *(const float4*)(ep + 4);
            Es[row][c0+0]=v0.x; Es[row][c0+1]=v0.y; Es[row][c0+2]=v0.z; Es[row][c0+3]=v0.w;
            Es[row][c0+4]=v1.x; Es[row][c0+5]=v1.y; Es[row][c0+6]=v1.z; Es[row][c0+7]=v1.w;
        }
        __syncthreads();
#pragma unroll
        for (int tt = 0; tt < 32; tt++) {
            float a[4], e[4];
#pragma unroll
            for (int i = 0; i < 4; i++) { a[i] = AWs[ty*4+i][tt]; e[i] = Es[tt][tx*4+i]; }
#pragma unroll
            for (int i = 0; i < 4; i++)
#pragma unroll
                for (int j = 0; j < 4; j++) acc[i][j] += a[i]*e[j];
        }
        __syncthreads();
    }
#pragma unroll
    for (int i = 0; i < 4; i++) {
        int n = ty*4 + i;
#pragma unroll
        for (int j = 0; j < 4; j++)
            dst[(((long)n)*BB + b)*D + h0 + tx*4 + j] = acc[i][j];
    }
}

// naive ctx (L=5, D=128)
__global__ void k_ctx(const float* __restrict__ aw, const float* __restrict__ enc,
                      float* __restrict__ dst, int L, int D) {
    int i = blockIdx.x * blockDim.x + threadIdx.x;
    if (i >= M2*KK) return;
    int m = i / D, h = i - m*D;
    int n = m / BB, b = m - n*BB;
    const float* awp = aw + ((long)b*NN + n)*L;
    float s = 0.f;
    for (int t = 0; t < L; t++) s += awp[t]*enc[((long)t*BB + b)*D + h];
    dst[i] = s;
}

__global__ void k_gate2(const float* __restrict__ gateW, const float* __restrict__ gateb,
                        float* __restrict__ gateout) {
    int m0 = blockIdx.x * 4;
    int tid = threadIdx.x;
    __shared__ float xs[4][GIN + 12];
#pragma unroll
    for (int r = 0; r < 4; r++) {
        int m = m0 + r, b = m & 31;
        for (int k = tid; k < GIN; k += 256) {
            float v;
            if (k < HH)        v = g_emb[(long)m*HH + k];
            else if (k < 2*HH) v = g_rnn[(long)m*HH + k - HH];
            else               v = g_e4[b*AN + k - 2*HH];
            xs[r][k] = v;
        }
    }
    __syncthreads();
    int w = tid >> 5, lane = tid & 31;
    for (int o = w; o < 4*AN; o += 8) {
        int r = o & 3, j = o >> 2;
        const float* wj = gateW + (long)j*GIN;
        float s = 0.f;
        for (int k = lane; k < GIN; k += 32) s += xs[r][k]*wj[k];
#pragma unroll
        for (int of = 16; of > 0; of >>= 1) s += __shfl_xor_sync(0xffffffffu, s, of);
        if (lane == 0) gateout[(long)(m0+r)*AN + j] = tanhf(s + gateb[j]);
    }
}

__global__ void k_scatter(const float* __restrict__ gate, const int* __restrict__ ids,
                          float* __restrict__ out0) {
    long i = (long)blockIdx.x * blockDim.x + threadIdx.x;
    if (i >= (long)M2*NASP) return;
    int m = (int)(i / NASP);
    int j = (int)(i - (long)m*NASP);
    if (!g_first[j]) return;
    float s = 0.f;
    int jj = j;
    while (jj >= 0) { s += gate[(long)m*AN + (jj % AN)]; jj = g_next[jj]; }
    out0[(long)m*VV + ids[j]] += s;
}

// ---------------- launcher ----------------
extern "C" void kernel_launch(void* const* d_in, const int* in_sizes, int n_in,
                              void* d_out, int out_size) {
    const int*   seq   = (const int*)  d_in[0];
    const float* lasth = (const float*)d_in[1];
    const float* enc1  = (const float*)d_in[2];
    const float* enc2  = (const float*)d_in[3];
    const float* enc3  = (const float*)d_in[4];
    const float* enc4  = (const float*)d_in[5];
    const int*   asp   = (const int*)  d_in[6];
    const float* emb   = (const float*)d_in[7];
    const float* Wih   = (const float*)d_in[8];
    const float* Whh   = (const float*)d_in[9];
    const float* bih   = (const float*)d_in[10];
    const float* bhh   = (const float*)d_in[11];
    const float* attnW = (const float*)d_in[12];
    const float* attnb = (const float*)d_in[13];
    const float* attnv = (const float*)d_in[14];
    const float* attrW = (const float*)d_in[15];
    const float* attrb = (const float*)d_in[16];
    const float* attrv = (const float*)d_in[17];
    const float* concW = (const float*)d_in[18];
    const float* concb = (const float*)d_in[19];
    const float* outW  = (const float*)d_in[20];
    const float* outb  = (const float*)d_in[21];
    const float* gateW = (const float*)d_in[22];
    const float* gateb = (const float*)d_in[23];
    const float* projW = (const float*)d_in[24];
    const float* projb = (const float*)d_in[25];
    float* out = (float*)d_out;

    const long O_HID  = (long)M2*VV;
    const long O_AW1  = O_HID + (long)BB*HH;
    const long O_AW2  = O_AW1 + (long)BB*NN*TT;
    const long O_AW3  = O_AW2 + (long)BB*NN*SS;
    const long O_GATE = O_AW3 + (long)BB*NN*AA;

    float *p_emb, *p_gi, *p_cout, *p_ctx1, *p_ctx2, *p_ctx3;
    uint32_t *p_wt, *p_at;
    cudaGetSymbolAddress((void**)&p_emb,  g_emb);
    cudaGetSymbolAddress((void**)&p_gi,   g_gi);
    cudaGetSymbolAddress((void**)&p_cout, g_cout);
    cudaGetSymbolAddress((void**)&p_ctx1, g_ctx1);
    cudaGetSymbolAddress((void**)&p_ctx2, g_ctx2);
    cudaGetSymbolAddress((void**)&p_ctx3, g_ctx3);
    cudaGetSymbolAddress((void**)&p_wt,   g_wt);
    cudaGetSymbolAddress((void**)&p_at,   g_at);

    const int GRU_SMEM = (6144 + 16384 + 3072 + 16) * 4;   // ~100KB
    cudaFuncSetAttribute(k_gru_all, cudaFuncAttributeMaxDynamicSharedMemorySize, GRU_SMEM);

    // 1) embedding
    k_embed<<<(M2*HH + 255)/256, 256>>>(seq, emb);

    // 2) gi = embedded @ Wih^T + bih (split-tf32, fp32-accurate)
    k_gemm_tf32s<<<dim3((3*HH)/128, M2/128), 256>>>(p_emb, Wih, bih, p_gi, HH, 3*HH);

    // 3) mega kernel: GRU (128 blocks) + shadow work (pack_w, uvec, e4, chain) on 20 SMs
    k_gru_all<<<GRU_BLOCKS + SIDE_BLOCKS, 512, GRU_SMEM>>>(
        lasth, Whh, bhh, out + O_HID,
        outW, attnW, attnv, attnb, attrW, attrv, attrb, enc4, projW, projb, asp);

    // 4) scalar attention dots (+ flag reset in block 0)
    {
        int warps = M2 + TT*BB + SS*BB + AA*BB;
        k_ac<<<(warps*32 + 255)/256, 256>>>(enc1, enc2, enc3);
    }

    // 5) merged softmaxes
    k_softmax_all<<<BB*NN + 256 + 8, 256>>>(out + O_AW1, out + O_AW2, out + O_AW3);

    // 6) contexts
    k_ctx_t<<<dim3(BB, HH/64), 256>>>(out + O_AW1, enc1, p_ctx1, TT, HH);
    k_ctx_t<<<dim3(BB, HH/64), 256>>>(out + O_AW2, enc2, p_ctx2, SS, HH);
    k_ctx  <<<(M2*KK + 255)/256, 256>>>(out + O_AW3, enc3, p_ctx3, AA, KK);

    // 7) concat GEMM (tf32) -> A pack -> packed tf32 big GEMM
    k_gemm_tf32<1><<<dim3(HH/128, M2/128), 128>>>(nullptr, concW, concb, p_cout, CIN, HH, 1);
    k_pack_a<<<(int)(((long)(M2/128)*64*8*32 + 255)/256), 256>>>(p_cout);
    k_gemm_tf32p<<<dim3(M2/128, VV/128), 128>>>((const uint4*)p_at, (const uint4*)p_wt, outb, out);

    // 8) gate path (e4 computed by side blocks)
    k_gate2<<<M2/4, 256>>>(gateW, gateb, out + O_GATE);

    // 9) deterministic scatter-add (chain computed by side blocks)
    k_scatter<<<(int)(((long)M2*NASP + 255)/256), 256>>>(out + O_GATE, asp, out);
}

// round 16
// speedup vs baseline: 1.0876x; 1.0190x over previous
#include <cuda_runtime.h>
#include <cuda_bf16.h>
#include <math.h>
#include <stdint.h>

#define NN 64
#define BB 32
#define HH 512
#define KK 128
#define VV 32000
#define TT 256
#define SS 32
#define AA 5
#define AN 20
#define M2 (NN*BB)          // 2048 rows
#define CIN (3*HH+KK)       // 1664
#define GIN (2*HH+AN)       // 1044
#define NASP 2000
#define GRU_BLOCKS 128
#define SIDE_BLOCKS 20
#define UCOLS (2*HH + HH + KK)   // 1664 projected columns

// ---------------- scratch (static device globals; no runtime alloc) ----------------
__device__ __align__(16) float g_emb[M2*HH];
__device__ __align__(16) float g_gi[M2*3*HH];
__device__ __align__(16) float g_hA[HH*BB];
__device__ __align__(16) float g_hB[HH*BB];
__device__ __align__(16) float g_rnn[M2*HH];
__device__ __align__(16) float g_u1[HH];
__device__ __align__(16) float g_u1e[HH];
__device__ __align__(16) float g_u3[HH];
__device__ __align__(16) float g_u3e[KK];
__device__ float g_bv[2];
__device__ float g_a1[M2], g_a3[M2];
__device__ float g_c1[TT*BB], g_c2[SS*BB], g_c3[AA*BB];
__device__ __align__(16) float g_ctx1[M2*HH];
__device__ __align__(16) float g_ctx2[M2*HH];
__device__ __align__(16) float g_ctx3[M2*KK];
__device__ __align__(16) uint32_t g_wt[VV*HH];      // 65.5 MB pre-rounded, fragment-packed W
__device__ __align__(16) uint32_t g_at[M2*HH];      // 4 MB fragment-packed A
__device__ float g_e4[BB*AN];
__device__ int g_first[NASP], g_next[NASP];
__device__ __align__(128) unsigned g_flag[GRU_BLOCKS*32] = {0};

// ---------------- contention-free flag barrier (GRU blocks only; monotonic) ----------------
__device__ __forceinline__ void gru_barrier(int bk, unsigned step) {
    __syncthreads();
    if (threadIdx.x == 0) {
        asm volatile("st.release.gpu.global.u32 [%0], %1;"
                     :: "l"(&g_flag[bk*32]), "r"(step) : "memory");
    }
    if (threadIdx.x < GRU_BLOCKS) {
        unsigned v;
        do {
            asm volatile("ld.acquire.gpu.global.u32 %0, [%1];"
                         : "=r"(v) : "l"(&g_flag[threadIdx.x*32]) : "memory");
        } while (v < step);
    }
    __syncthreads();
}

// ---------------- helpers ----------------
__device__ __forceinline__ uint32_t smem_u32(const void* p) {
    uint32_t a;
    asm("{ .reg .u64 t; cvta.to.shared.u64 t, %1; cvt.u32.u64 %0, t; }" : "=r"(a) : "l"(p));
    return a;
}
__device__ __forceinline__ uint32_t f2tf(float x) {
    uint32_t u; asm("cvt.rna.tf32.f32 %0, %1;" : "=r"(u) : "f"(x)); return u;
}
__device__ __forceinline__ void split_tf32(float x, uint32_t& hi, uint32_t& lo) {
    hi = f2tf(x);
    float r = x - __uint_as_float(hi);
    lo = f2tf(r);
}
__device__ __forceinline__ void mma_tf32(float& c0, float& c1, float& c2, float& c3,
                                         uint32_t a0, uint32_t a1, uint32_t a2, uint32_t a3,
                                         uint32_t b0, uint32_t b1) {
    asm volatile("mma.sync.aligned.m16n8k8.row.col.f32.tf32.tf32.f32 "
                 "{%0,%1,%2,%3},{%4,%5,%6,%7},{%8,%9},{%0,%1,%2,%3};"
                 : "+f"(c0), "+f"(c1), "+f"(c2), "+f"(c3)
                 : "r"(a0), "r"(a1), "r"(a2), "r"(a3), "r"(b0), "r"(b1));
}
__device__ __forceinline__ void cpa16(uint32_t saddr, const void* gaddr) {
    asm volatile("cp.async.cg.shared.global [%0], [%1], 16;" :: "r"(saddr), "l"(gaddr));
}

// ---------------- kernels ----------------

__global__ void k_embed(const int* __restrict__ seq, const float* __restrict__ emb) {
    int i = blockIdx.x * blockDim.x + threadIdx.x;
    if (i < M2*HH) {
        int m = i / HH, h = i - m*HH;
        g_emb[i] = emb[(long)seq[m]*HH + h];
    }
}

// ---------------- packed tf32 GEMM: C[M2,VV] = A[M2,HH] * W[VV,HH]^T + bias ----------------
__global__ __launch_bounds__(128, 2)
void k_gemm_tf32p(const uint4* __restrict__ At, const uint4* __restrict__ Wt,
                  const float* __restrict__ bias, float* __restrict__ C) {
    __shared__ __align__(16) uint4 As[2][512];
    __shared__ __align__(16) uint4 Bs[2][512];
    int tid = threadIdx.x;
    int warp = tid >> 5, lane = tid & 31;
    int wm = warp & 1, wnp = warp >> 1;
    int lq = lane >> 2, lr = lane & 3;
    int m0 = blockIdx.x * 128, n0 = blockIdx.y * 128;
    const uint4* Ab = At + (long)blockIdx.x * 16384;
    const uint4* Bb = Wt + (long)blockIdx.y * 16384;

    float acc[4][8][4];
#pragma unroll
    for (int i = 0; i < 4; i++)
#pragma unroll
        for (int j = 0; j < 8; j++)
#pragma unroll
            for (int c = 0; c < 4; c++) acc[i][j][c] = 0.f;

#pragma unroll
    for (int i = 0; i < 4; i++) {
        cpa16(smem_u32(&As[0][i*128 + tid]), Ab + i*128 + tid);
        cpa16(smem_u32(&Bs[0][i*128 + tid]), Bb + i*128 + tid);
    }
    asm volatile("cp.async.commit_group;");

    int buf = 0;
    const int NK = HH / 16;
    for (int c = 0; c < NK; c++) {
        asm volatile("cp.async.wait_group 0;" ::: "memory");
        __syncthreads();
        if (c + 1 < NK) {
            const uint4* an = Ab + (c+1)*512;
            const uint4* bn = Bb + (c+1)*512;
#pragma unroll
            for (int i = 0; i < 4; i++) {
                cpa16(smem_u32(&As[buf^1][i*128 + tid]), an + i*128 + tid);
                cpa16(smem_u32(&Bs[buf^1][i*128 + tid]), bn + i*128 + tid);
            }
            asm volatile("cp.async.commit_group;");
        }
#pragma unroll
        for (int kk = 0; kk < 2; kk++) {
            uint4 av[4], bv[4];
#pragma unroll
            for (int ms = 0; ms < 4; ms++)
                av[ms] = As[buf][kk*256 + (wm*4 + ms)*32 + lane];
#pragma unroll
            for (int p = 0; p < 4; p++)
                bv[p] = Bs[buf][kk*256 + (wnp*4 + p)*32 + lane];
#pragma unroll
            for (int ms = 0; ms < 4; ms++)
#pragma unroll
                for (int p = 0; p < 4; p++) {
                    mma_tf32(acc[ms][2*p][0], acc[ms][2*p][1], acc[ms][2*p][2], acc[ms][2*p][3],
                             av[ms].x, av[ms].y, av[ms].z, av[ms].w, bv[p].x, bv[p].y);
                    mma_tf32(acc[ms][2*p+1][0], acc[ms][2*p+1][1], acc[ms][2*p+1][2], acc[ms][2*p+1][3],
                             av[ms].x, av[ms].y, av[ms].z, av[ms].w, bv[p].z, bv[p].w);
                }
        }
        buf ^= 1;
    }
#pragma unroll
    for (int ms = 0; ms < 4; ms++) {
        int row = m0 + wm*64 + ms*16 + lq;
#pragma unroll
        for (int ns = 0; ns < 8; ns++) {
            int col = n0 + wnp*64 + ns*8 + lr*2;
            float b0 = bias[col], b1 = bias[col+1];
            *(float2*)(C + (long)row*VV + col)     = make_float2(acc[ms][ns][0] + b0, acc[ms][ns][1] + b1);
            *(float2*)(C + (long)(row+8)*VV + col) = make_float2(acc[ms][ns][2] + b0, acc[ms][ns][3] + b1);
        }
    }
}

// ---------------- mega kernel: persistent GRU (0..127) + side work (128..147) ----------------
__global__ __launch_bounds__(512, 1)
void k_gru_all(const float* __restrict__ lasth, const float* __restrict__ Whh,
               const float* __restrict__ bhh, float* __restrict__ hid,
               const float* __restrict__ outW,
               const float* __restrict__ attnW, const float* __restrict__ attnv,
               const float* __restrict__ attnb, const float* __restrict__ attrW,
               const float* __restrict__ attrv, const float* __restrict__ attrb,
               const float* __restrict__ enc4, const float* __restrict__ projW,
               const float* __restrict__ projb, const int* __restrict__ asp) {
    extern __shared__ __align__(16) float dsm[];
    int tid = threadIdx.x, bk = blockIdx.x;

    if (bk >= GRU_BLOCKS) {
        // ===================== side work on 20 spare SMs =====================
        int sb = bk - GRU_BLOCKS;
        // (a) W fragment pack (grid-strided over side blocks)
        const long TOTW = (long)(VV/128)*64*8*32;
        for (long i = (long)sb*512 + tid; i < TOTW; i += (long)SIDE_BLOCKS*512) {
            int lane = (int)(i & 31), fp = (int)((i >> 5) & 7), s = (int)((i >> 8) & 63);
            long nb = i >> 14;
            int lq = lane >> 2, lr = lane & 3;
            int k = s*8 + lr;
            long ne = nb*128 + fp*16 + lq;
            uint4 v;
            v.x = f2tf(outW[ne*HH + k]);
            v.y = f2tf(outW[ne*HH + k + 4]);
            v.z = f2tf(outW[(ne+8)*HH + k]);
            v.w = f2tf(outW[(ne+8)*HH + k + 4]);
            ((uint4*)g_wt)[i] = v;
        }
        // (b) uvec: full-column warp dots
        {
            int gw2 = sb*16 + (tid >> 5);
            int lane = tid & 31;
            for (int t = gw2; t < UCOLS + 2; t += SIDE_BLOCKS*16) {
                float s = 0.f;
                if (t < UCOLS) {
                    const float* W; const float* v; int ld; int c;
                    if (t < 2*HH) { W = attnW; v = attnv; ld = 2*HH;    c = t; }
                    else          { W = attrW; v = attrv; ld = HH + KK; c = t - 2*HH; }
                    for (int h = lane; h < HH; h += 32) s += W[(long)h*ld + c]*v[h];
#pragma unroll
                    for (int o = 16; o > 0; o >>= 1) s += __shfl_xor_sync(0xffffffffu, s, o);
                    if (lane == 0) {
                        if (t < HH)            g_u1[t] = s;
                        else if (t < 2*HH)     g_u1e[t - HH] = s;
                        else if (t < 3*HH)     g_u3[t - 2*HH] = s;
                        else                   g_u3e[t - 3*HH] = s;
                    }
                } else {
                    int w = t - UCOLS;
                    const float* bp = w ? attrb : attnb;
                    const float* vp = w ? attrv : attnv;
                    for (int h = lane; h < HH; h += 32) s += bp[h]*vp[h];
#pragma unroll
                    for (int o = 16; o > 0; o >>= 1) s += __shfl_xor_sync(0xffffffffu, s, o);
                    if (lane == 0) g_bv[w] = s;
                }
            }
        }
        // (c) e4 projection (block sb==0)
        if (sb == 0) {
            for (int i = tid; i < BB*AN; i += 512) {
                int b = i / AN, j = i - b*AN;
                float s = projb[j];
                for (int k = 0; k < AN; k++) s += enc4[(0*BB + b)*AN + k]*projW[j*2*AN + k];
                for (int k = 0; k < AN; k++) s += enc4[(1*BB + b)*AN + k]*projW[j*2*AN + AN + k];
                g_e4[i] = s;
            }
        }
        // (d) duplicate-chain (block sb==1), smem lockstep scan
        if (sb == 1) {
            int* sid = (int*)dsm;
            for (int k = tid; k < NASP; k += 512) sid[k] = asp[k];
            __syncthreads();
            for (int j = tid; j < NASP; j += 512) {
                int v = sid[j];
                int fst = 1, nxt = -1;
                for (int j2 = 0; j2 < NASP; j2++) {
                    int w = sid[j2];
                    if (w == v) {
                        if (j2 < j) fst = 0;
                        else if (j2 > j && nxt < 0) nxt = j2;
                    }
                }
                g_first[j] = fst;
                g_next[j]  = nxt;
            }
        }
        return;
    }

    // ===================== persistent GRU =====================
    float* sw   = dsm;                    // 6144
    float* sh   = dsm + 6144;             // 16384
    float* part = dsm + 6144 + 16384;     // 3072
    float* sbv  = part + 3072;            // 12

    int b  = tid & 31;
    int ju = (tid >> 5) & 1;
    int kq = tid >> 6;

    for (int r = 0; r < 12; r++) {
        int g = r / 4, j = r % 4;
        int rowi = g*HH + bk*4 + j;
        for (int k = tid; k < HH; k += 512) sw[(g*4 + j)*HH + k] = Whh[(long)rowi*HH + k];
    }
    if (tid < 12) sbv[tid] = bhh[(tid/4)*HH + bk*4 + (tid%4)];

    if (tid < 128) {
        int idx = bk*128 + tid;
        int k = idx >> 5, bb = idx & 31;
        __stcg(&g_hA[idx], lasth[bb*HH + k]);
    }
    gru_barrier(bk, 1u);

    float* hp = g_hA;
    float* hc = g_hB;
    int u0 = ju*2;
    const float* wr0 = sw + (0*4 + u0    )*HH;
    const float* wr1 = sw + (0*4 + u0 + 1)*HH;
    const float* wz0 = sw + (1*4 + u0    )*HH;
    const float* wz1 = sw + (1*4 + u0 + 1)*HH;
    const float* wn0 = sw + (2*4 + u0    )*HH;
    const float* wn1 = sw + (2*4 + u0 + 1)*HH;
    int k0 = kq * 64;

    for (int n = 0; n < NN; n++) {
#pragma unroll
        for (int i = 0; i < 8; i++) {
            int f = tid + i*512;
            float4 v = __ldcg((const float4*)hp + f);
            *(float4*)(sh + 4*f) = v;
        }
        __syncthreads();

        float sr0 = 0.f, sz0 = 0.f, sn0 = 0.f;
        float sr1 = 0.f, sz1 = 0.f, sn1 = 0.f;
#pragma unroll 4
        for (int k = k0; k < k0 + 64; k += 4) {
            float h0 = sh[(k+0)*BB + b];
            float h1 = sh[(k+1)*BB + b];
            float h2 = sh[(k+2)*BB + b];
            float h3 = sh[(k+3)*BB + b];
            float4 a;
            a = *(const float4*)(wr0 + k); sr0 += a.x*h0 + a.y*h1 + a.z*h2 + a.w*h3;
            a = *(const float4*)(wz0 + k); sz0 += a.x*h0 + a.y*h1 + a.z*h2 + a.w*h3;
            a = *(const float4*)(wn0 + k); sn0 += a.x*h0 + a.y*h1 + a.z*h2 + a.w*h3;
            a = *(const float4*)(wr1 + k); sr1 += a.x*h0 + a.y*h1 + a.z*h2 + a.w*h3;
            a = *(const float4*)(wz1 + k); sz1 += a.x*h0 + a.y*h1 + a.z*h2 + a.w*h3;
            a = *(const float4*)(wn1 + k); sn1 += a.x*h0 + a.y*h1 + a.z*h2 + a.w*h3;
        }
        part[((0*4 + u0    )*8 + kq)*32 + b] = sr0;
        part[((1*4 + u0    )*8 + kq)*32 + b] = sz0;
        part[((2*4 + u0    )*8 + kq)*32 + b] = sn0;
        part[((0*4 + u0 + 1)*8 + kq)*32 + b] = sr1;
        part[((1*4 + u0 + 1)*8 + kq)*32 + b] = sz1;
        part[((2*4 + u0 + 1)*8 + kq)*32 + b] = sn1;
        __syncthreads();

        if (kq < 2) {
            int jgl = u0 + kq;
            int jg  = bk*4 + jgl;
            float sr = 0.f, sz = 0.f, sn = 0.f;
#pragma unroll
            for (int q = 0; q < 8; q++) {
                sr += part[((0*4 + jgl)*8 + q)*32 + b];
                sz += part[((1*4 + jgl)*8 + q)*32 + b];
                sn += part[((2*4 + jgl)*8 + q)*32 + b];
            }
            float hold = sh[jg*BB + b];
            const float* gi = g_gi + ((long)(n*BB + b))*(3*HH);
            float rr = 1.f/(1.f + expf(-(gi[jg]        + sr + sbv[0*4 + jgl])));
            float zz = 1.f/(1.f + expf(-(gi[HH + jg]   + sz + sbv[1*4 + jgl])));
            float nn = tanhf(gi[2*HH + jg] + rr*(sn + sbv[2*4 + jgl]));
            float hn = (1.f - zz)*nn + zz*hold;
            __stcg(hc + jg*BB + b, hn);
            g_rnn[((long)(n*BB + b))*HH + jg] = hn;
            if (n == NN-1) hid[b*HH + jg] = hn;
        }
        if (n < NN-1) gru_barrier(bk, (unsigned)(n + 2));
        float* t = hp; hp = hc; hc = t;
    }
}

// ---------------- concat tf32 GEMM with FUSED fragment pack (writes g_at directly) ----------------
__device__ __forceinline__ const float* concat_src(int m, int k) {
    if (k < HH)        return g_rnn  + (long)m*HH + k;
    if (k < 2*HH)      return g_ctx1 + (long)m*HH + (k - HH);
    if (k < 3*HH)      return g_ctx2 + (long)m*HH + (k - 2*HH);
    return g_ctx3 + (long)m*KK + (k - 3*HH);
}

// grid (HH/128=4, M2/128=16), 128 threads, dyn smem: As|Bs (10240 f) + tile 128x132
__global__ __launch_bounds__(128, 1)
void k_gemm_cpack(const float* __restrict__ W, const float* __restrict__ bias) {
    extern __shared__ __align__(16) float ds2[];
    float* AsB = ds2;                 // As: [2][128][20] = 5120 floats
    float* BsB = ds2 + 5120;          // Bs: same
    float* tile = ds2 + 10240;        // [128][132]
    int tid = threadIdx.x;
    int warp = tid >> 5, lane = tid & 31;
    int wm = warp & 1, wnp = warp >> 1;
    int lq = lane >> 2, lr = lane & 3;
    int m0 = blockIdx.y * 128, n0 = blockIdx.x * 128;

    float acc[4][8][4];
#pragma unroll
    for (int i = 0; i < 4; i++)
#pragma unroll
        for (int j = 0; j < 8; j++)
#pragma unroll
            for (int c = 0; c < 4; c++) acc[i][j][c] = 0.f;

    const int NK = CIN / 16;
#pragma unroll
    for (int i = 0; i < 4; i++) {
        int idx = i*128 + tid, row = idx >> 2, kc = idx & 3;
        cpa16(smem_u32(&AsB[(0*128 + row)*20 + kc*4]), concat_src(m0+row, kc*4));
        cpa16(smem_u32(&BsB[(0*128 + row)*20 + kc*4]), W + (long)(n0+row)*CIN + kc*4);
    }
    asm volatile("cp.async.commit_group;");

    int buf = 0;
    for (int ks = 0; ks < NK; ks++) {
        asm volatile("cp.async.wait_group 0;");
        __syncthreads();
        if (ks + 1 < NK) {
#pragma unroll
            for (int i = 0; i < 4; i++) {
                int idx = i*128 + tid, row = idx >> 2, kc = idx & 3;
                int kpos = (ks+1)*16 + kc*4;
                cpa16(smem_u32(&AsB[((buf^1)*128 + row)*20 + kc*4]), concat_src(m0+row, kpos));
                cpa16(smem_u32(&BsB[((buf^1)*128 + row)*20 + kc*4]), W + (long)(n0+row)*CIN + kpos);
            }
            asm volatile("cp.async.commit_group;");
        }
#pragma unroll
        for (int kk = 0; kk < 16; kk += 8) {
            uint32_t af[4][4], bf[8][2];
#pragma unroll
            for (int ms = 0; ms < 4; ms++) {
                int rb = wm*64 + ms*16;
                af[ms][0] = f2tf(AsB[(buf*128 + rb + lq    )*20 + kk + lr    ]);
                af[ms][1] = f2tf(AsB[(buf*128 + rb + lq + 8)*20 + kk + lr    ]);
                af[ms][2] = f2tf(AsB[(buf*128 + rb + lq    )*20 + kk + lr + 4]);
                af[ms][3] = f2tf(AsB[(buf*128 + rb + lq + 8)*20 + kk + lr + 4]);
            }
#pragma unroll
            for (int ns = 0; ns < 8; ns++) {
                int nb = wnp*64 + ns*8;
                bf[ns][0] = f2tf(BsB[(buf*128 + nb + lq)*20 + kk + lr    ]);
                bf[ns][1] = f2tf(BsB[(buf*128 + nb + lq)*20 + kk + lr + 4]);
            }
#pragma unroll
            for (int ms = 0; ms < 4; ms++)
#pragma unroll
                for (int ns = 0; ns < 8; ns++)
                    mma_tf32(acc[ms][ns][0], acc[ms][ns][1], acc[ms][ns][2], acc[ms][ns][3],
                             af[ms][0], af[ms][1], af[ms][2], af[ms][3],
                             bf[ns][0], bf[ns][1]);
        }
        buf ^= 1;
    }
    // stage tanh(acc + bias) into smem tile (local layout [row][col], pitch 132)
#pragma unroll
    for (int ms = 0; ms < 4; ms++) {
        int lrow = wm*64 + ms*16 + lq;
#pragma unroll
        for (int ns = 0; ns < 8; ns++) {
            int lcol = wnp*64 + ns*8 + lr*2;
            float b0 = bias[n0 + lcol], b1 = bias[n0 + lcol + 1];
            tile[lrow*132 + lcol]       = tanhf(acc[ms][ns][0] + b0);
            tile[lrow*132 + lcol + 1]   = tanhf(acc[ms][ns][1] + b1);
            tile[(lrow+8)*132 + lcol]   = tanhf(acc[ms][ns][2] + b0);
            tile[(lrow+8)*132 + lcol+1] = tanhf(acc[ms][ns][3] + b1);
        }
    }
    __syncthreads();
    // pack this block's 16 k8-slices of g_at
    int mb = blockIdx.y, xb = blockIdx.x;
    for (int t = tid; t < 4096; t += 128) {
        int ln = t & 31, fp = (t >> 5) & 7, sl = t >> 8;
        int lq2 = ln >> 2, lr2 = ln & 3;
        uint4 v;
        v.x = f2tf(tile[(fp*16 + lq2    )*132 + sl*8 + lr2    ]);
        v.y = f2tf(tile[(fp*16 + lq2 + 8)*132 + sl*8 + lr2    ]);
        v.z = f2tf(tile[(fp*16 + lq2    )*132 + sl*8 + lr2 + 4]);
        v.w = f2tf(tile[(fp*16 + lq2 + 8)*132 + sl*8 + lr2 + 4]);
        ((uint4*)g_at)[(((long)mb*64 + xb*16 + sl)*8 + fp)*32 + ln] = v;
    }
}

// split-precision tf32 GEMM (fp32-accurate) for gi
__global__ __launch_bounds__(256)
void k_gemm_tf32s(const float* __restrict__ A, const float* __restrict__ W,
                  const float* __restrict__ bias, float* __restrict__ C,
                  int Kd, int ldC) {
    __shared__ __align__(16) float As[2][128][20];
    __shared__ __align__(16) float Bs[2][128][20];
    int tid = threadIdx.x;
    int warp = tid >> 5, lane = tid & 31;
    int wm = warp & 1, wn = warp >> 1;
    int lq = lane >> 2, lr = lane & 3;
    int m0 = blockIdx.y * 128, n0 = blockIdx.x * 128;

    float acc[4][4][4];
#pragma unroll
    for (int i = 0; i < 4; i++)
#pragma unroll
        for (int j = 0; j < 4; j++)
#pragma unroll
            for (int c = 0; c < 4; c++) acc[i][j][c] = 0.f;

    const int NK = Kd / 16;
#pragma unroll
    for (int i = 0; i < 2; i++) {
        int idx = i*256 + tid, row = idx >> 2, kc = idx & 3;
        cpa16(smem_u32(&As[0][row][kc*4]), A + (long)(m0+row)*Kd + kc*4);
        cpa16(smem_u32(&Bs[0][row][kc*4]), W + (long)(n0+row)*Kd + kc*4);
    }
    asm volatile("cp.async.commit_group;");

    int buf = 0;
    for (int ks = 0; ks < NK; ks++) {
        asm volatile("cp.async.wait_group 0;");
        __syncthreads();
        if (ks + 1 < NK) {
#pragma unroll
            for (int i = 0; i < 2; i++) {
                int idx = i*256 + tid, row = idx >> 2, kc = idx & 3;
                int kpos = (ks+1)*16 + kc*4;
                cpa16(smem_u32(&As[buf^1][row][kc*4]), A + (long)(m0+row)*Kd + kpos);
                cpa16(smem_u32(&Bs[buf^1][row][kc*4]), W + (long)(n0+row)*Kd + kpos);
            }
            asm volatile("cp.async.commit_group;");
        }
#pragma unroll
        for (int kk = 0; kk < 16; kk += 8) {
            uint32_t ah[4][4], al[4][4], bh[4][2], bl[4][2];
#pragma unroll
            for (int ms = 0; ms < 4; ms++) {
                int rb = wm*64 + ms*16;
                split_tf32(As[buf][rb + lq    ][kk + lr    ], ah[ms][0], al[ms][0]);
                split_tf32(As[buf][rb + lq + 8][kk + lr    ], ah[ms][1], al[ms][1]);
                split_tf32(As[buf][rb + lq    ][kk + lr + 4], ah[ms][2], al[ms][2]);
                split_tf32(As[buf][rb + lq + 8][kk + lr + 4], ah[ms][3], al[ms][3]);
            }
#pragma unroll
            for (int ns = 0; ns < 4; ns++) {
                int nb = wn*32 + ns*8;
                split_tf32(Bs[buf][nb + lq][kk + lr    ], bh[ns][0], bl[ns][0]);
                split_tf32(Bs[buf][nb + lq][kk + lr + 4], bh[ns][1], bl[ns][1]);
            }
#pragma unroll
            for (int ms = 0; ms < 4; ms++)
#pragma unroll
                for (int ns = 0; ns < 4; ns++) {
                    mma_tf32(acc[ms][ns][0], acc[ms][ns][1], acc[ms][ns][2], acc[ms][ns][3],
                             ah[ms][0], ah[ms][1], ah[ms][2], ah[ms][3], bh[ns][0], bh[ns][1]);
                    mma_tf32(acc[ms][ns][0], acc[ms][ns][1], acc[ms][ns][2], acc[ms][ns][3],
                             ah[ms][0], ah[ms][1], ah[ms][2], ah[ms][3], bl[ns][0], bl[ns][1]);
                    mma_tf32(acc[ms][ns][0], acc[ms][ns][1], acc[ms][ns][2], acc[ms][ns][3],
                             al[ms][0], al[ms][1], al[ms][2], al[ms][3], bh[ns][0], bh[ns][1]);
                }
        }
        buf ^= 1;
    }
#pragma unroll
    for (int ms = 0; ms < 4; ms++) {
        int row = m0 + wm*64 + ms*16 + lq;
#pragma unroll
        for (int ns = 0; ns < 4; ns++) {
            int col = n0 + wn*32 + ns*8 + lr*2;
            float b0 = bias[col], b1 = bias[col+1];
            *(float2*)(C + (long)row*ldC + col)     = make_float2(acc[ms][ns][0] + b0, acc[ms][ns][1] + b1);
            *(float2*)(C + (long)(row+8)*ldC + col) = make_float2(acc[ms][ns][2] + b0, acc[ms][ns][3] + b1);
        }
    }
}

// all scalar attention dot products (a-dots + c-dots); block 0 also resets GRU flags
__global__ void k_ac(const float* __restrict__ enc1, const float* __restrict__ enc2,
                     const float* __restrict__ enc3) {
    if (blockIdx.x == 0 && threadIdx.x < GRU_BLOCKS) g_flag[threadIdx.x*32] = 0u;
    int gw = (blockIdx.x * blockDim.x + threadIdx.x) >> 5;
    int lane = threadIdx.x & 31;
    const int E_A = M2, E_C1 = E_A + TT*BB, E_C2 = E_C1 + SS*BB, E_C3 = E_C2 + AA*BB;
    if (gw >= E_C3) return;
    if (gw < E_A) {
        const float4* x = (const float4*)(g_rnn + (long)gw*HH);
        const float4* u1 = (const float4*)g_u1;
        const float4* u3 = (const float4*)g_u3;
        float s1 = 0.f, s3 = 0.f;
#pragma unroll
        for (int k = lane; k < HH/4; k += 32) {
            float4 xv = x[k], a = u1[k], b = u3[k];
            s1 += xv.x*a.x + xv.y*a.y + xv.z*a.z + xv.w*a.w;
            s3 += xv.x*b.x + xv.y*b.y + xv.z*b.z + xv.w*b.w;
        }
#pragma unroll
        for (int o = 16; o > 0; o >>= 1) {
            s1 += __shfl_xor_sync(0xffffffffu, s1, o);
            s3 += __shfl_xor_sync(0xffffffffu, s3, o);
        }
        if (lane == 0) { g_a1[gw] = s1 + g_bv[0]; g_a3[gw] = s3 + g_bv[1]; }
        return;
    }
    const float* x; const float* u; float* dst; int len = HH;
    if (gw < E_C1)      { int m = gw - E_A;   x = enc1 + (long)m*HH; u = g_u1e; dst = g_c1 + m; }
    else if (gw < E_C2) { int m = gw - E_C1;  x = enc2 + (long)m*HH; u = g_u1e; dst = g_c2 + m; }
    else                { int m = gw - E_C2;  x = enc3 + (long)m*KK; u = g_u3e; dst = g_c3 + m; len = KK; }
    const float4* x4 = (const float4*)x;
    const float4* u4 = (const float4*)u;
    float s = 0.f;
    for (int k = lane; k < len/4; k += 32) {
        float4 xv = x4[k], uv = u4[k];
        s += xv.x*uv.x + xv.y*uv.y + xv.z*uv.z + xv.w*uv.w;
    }
#pragma unroll
    for (int o = 16; o > 0; o >>= 1) s += __shfl_xor_sync(0xffffffffu, s, o);
    if (lane == 0) *dst = s;
}

// merged softmaxes
__global__ void k_softmax_all(float* __restrict__ aw1, float* __restrict__ aw2,
                              float* __restrict__ aw3) {
    int blk = blockIdx.x;
    int tid = threadIdx.x;
    if (blk < BB*NN) {
        int bn = blk;
        int b = bn / NN, n = bn - b*NN;
        float e  = tanhf(g_a1[n*BB + b] + g_c1[tid*BB + b]);
        float ex = expf(e);
        __shared__ float red[8];
        __shared__ float stot;
        float s = ex;
#pragma unroll
        for (int o = 16; o > 0; o >>= 1) s += __shfl_xor_sync(0xffffffffu, s, o);
        if ((tid & 31) == 0) red[tid >> 5] = s;
        __syncthreads();
        if (tid == 0) { float tt = 0.f; for (int i = 0; i < 8; i++) tt += red[i]; stot = tt; }
        __syncthreads();
        aw1[(long)bn*TT + tid] = ex / stot;
    } else if (blk < BB*NN + 256) {
        int gw = (blk - BB*NN)*8 + (tid >> 5);
        int b = gw / NN, n = gw - b*NN;
        int s2 = tid & 31;
        float e  = tanhf(g_a1[n*BB + b] + g_c2[s2*BB + b]);
        float ex = expf(e);
        float tot = ex;
#pragma unroll
        for (int o = 16; o > 0; o >>= 1) tot += __shfl_xor_sync(0xffffffffu, tot, o);
        aw2[(long)gw*SS + s2] = ex / tot;
    } else {
        int bn = (blk - BB*NN - 256)*256 + tid;
        if (bn >= BB*NN) return;
        int b = bn / NN, n = bn - b*NN;
        float ex[AA]; float tot = 0.f;
#pragma unroll
        for (int a = 0; a < AA; a++) {
            ex[a] = expf(tanhf(g_a3[n*BB + b] + g_c3[a*BB + b]));
            tot += ex[a];
        }
#pragma unroll
        for (int a = 0; a < AA; a++) aw3[(long)bn*AA + a] = ex[a] / tot;
    }
}

// ---------------- merged tail: ctx1/ctx2 (tiled), ctx3 (naive), gate ----------------
__global__ __launch_bounds__(256)
void k_tail(const float* __restrict__ aw1, const float* __restrict__ enc1,
            const float* __restrict__ aw2, const float* __restrict__ enc2,
            const float* __restrict__ aw3, const float* __restrict__ enc3,
            const float* __restrict__ gateW, const float* __restrict__ gateb,
            float* __restrict__ gateout) {
    __shared__ __align__(16) char sbuf[17280];
    int blk = blockIdx.x;
    int tid = threadIdx.x;

    if (blk < 512) {
        // tiled ctx for enc1 (blk<256) or enc2
        const float* aw  = (blk < 256) ? aw1 : aw2;
        const float* enc = (blk < 256) ? enc1 : enc2;
        float* dst = (blk < 256) ? g_ctx1 : g_ctx2;
        int L = (blk < 256) ? TT : SS;
        int lb = blk & 255;
        int b  = lb & 31;
        int h0 = (lb >> 5) * 64;
        float (*AWs)[33] = (float(*)[33])sbuf;
        float (*Es)[68]  = (float(*)[68])(sbuf + 8448);
        int tx = tid & 15, ty = tid >> 4;
        float acc[4][4] = {};
        for (int t0 = 0; t0 < L; t0 += 32) {
            {
                int row = tid >> 2, c0 = (tid & 3) * 8;
                const float* ap = aw + ((long)b*NN + row)*L + t0 + c0;
                float4 v0 = *(const float4*)ap;
                float4 v1 = *(const float4*)(ap + 4);
                AWs[row][c0+0]=v0.x; AWs[row][c0+1]=v0.y; AWs[row][c0+2]=v0.z; AWs[row][c0+3]=v0.w;
                AWs[row][c0+4]=v1.x; AWs[row][c0+5]=v1.y; AWs[row][c0+6]=v1.z; AWs[row][c0+7]=v1.w;
            }
            {
                int row = tid >> 3, c0 = (tid & 7) * 8;
                const float* ep = enc + (((long)(t0+row))*BB + b)*HH + h0 + c0;
                float4 v0 = *(const float4*)ep;
                float4 v1 = *(const float4*)(ep + 4);
                Es[row][c0+0]=v0.x; Es[row][c0+1]=v0.y; Es[row][c0+2]=v0.z; Es[row][c0+3]=v0.w;
                Es[row][c0+4]=v1.x; Es[row][c0+5]=v1.y; Es[row][c0+6]=v1.z; Es[row][c0+7]=v1.w;
            }
            __syncthreads();
#pragma unroll
            for (int tt = 0; tt < 32; tt++) {
                float a[4], e[4];
#pragma unroll
                for (int i = 0; i < 4; i++) { a[i] = AWs[ty*4+i][tt]; e[i] = Es[tt][tx*4+i]; }
#pragma unroll
                for (int i = 0; i < 4; i++)
#pragma unroll
                    for (int j = 0; j < 4; j++) acc[i][j] += a[i]*e[j];
            }
            __syncthreads();
        }
#pragma unroll
        for (int i = 0; i < 4; i++) {
            int n = ty*4 + i;
#pragma unroll
            for (int j = 0; j < 4; j++)
                dst[(((long)n)*BB + b)*HH + h0 + tx*4 + j] = acc[i][j];
        }
    } else if (blk < 1536) {
        // naive ctx3
        int i = (blk - 512)*256 + tid;
        if (i >= M2*KK) return;
        int m = i / KK, h = i - m*KK;
        int n = m / BB, b = m - n*BB;
        const float* awp = aw3 + ((long)b*NN + n)*AA;
        float s = 0.f;
        for (int t = 0; t < AA; t++) s += awp[t]*enc3[((long)t*BB + b)*KK + h];
        g_ctx3[i] = s;
    } else {
        // gate
        int m0 = (blk - 1536)*4;
        float (*xs)[GIN + 12] = (float(*)[GIN + 12])sbuf;
#pragma unroll
        for (int r = 0; r < 4; r++) {
            int m = m0 + r, b = m & 31;
            for (int k = tid; k < GIN; k += 256) {
                float v;
                if (k < HH)        v = g_emb[(long)m*HH + k];
                else if (k < 2*HH) v = g_rnn[(long)m*HH + k - HH];
                else               v = g_e4[b*AN + k - 2*HH];
                xs[r][k] = v;
            }
        }
        __syncthreads();
        int w = tid >> 5, lane = tid & 31;
        for (int o = w; o < 4*AN; o += 8) {
            int r = o & 3, j = o >> 2;
            const float* wj = gateW + (long)j*GIN;
            float s = 0.f;
            for (int k = lane; k < GIN; k += 32) s += xs[r][k]*wj[k];
#pragma unroll
            for (int of = 16; of > 0; of >>= 1) s += __shfl_xor_sync(0xffffffffu, s, of);
            if (lane == 0) gateout[(long)(m0+r)*AN + j] = tanhf(s + gateb[j]);
        }
    }
}

__global__ void k_scatter(const float* __restrict__ gate, const int* __restrict__ ids,
                          float* __restrict__ out0) {
    long i = (long)blockIdx.x * blockDim.x + threadIdx.x;
    if (i >= (long)M2*NASP) return;
    int m = (int)(i / NASP);
    int j = (int)(i - (long)m*NASP);
    if (!g_first[j]) return;
    float s = 0.f;
    int jj = j;
    while (jj >= 0) { s += gate[(long)m*AN + (jj % AN)]; jj = g_next[jj]; }
    out0[(long)m*VV + ids[j]] += s;
}

// ---------------- launcher ----------------
extern "C" void kernel_launch(void* const* d_in, const int* in_sizes, int n_in,
                              void* d_out, int out_size) {
    const int*   seq   = (const int*)  d_in[0];
    const float* lasth = (const float*)d_in[1];
    const float* enc1  = (const float*)d_in[2];
    const float* enc2  = (const float*)d_in[3];
    const float* enc3  = (const float*)d_in[4];
    const float* enc4  = (const float*)d_in[5];
    const int*   asp   = (const int*)  d_in[6];
    const float* emb   = (const float*)d_in[7];
    const float* Wih   = (const float*)d_in[8];
    const float* Whh   = (const float*)d_in[9];
    const float* bih   = (const float*)d_in[10];
    const float* bhh   = (const float*)d_in[11];
    const float* attnW = (const float*)d_in[12];
    const float* attnb = (const float*)d_in[13];
    const float* attnv = (const float*)d_in[14];
    const float* attrW = (const float*)d_in[15];
    const float* attrb = (const float*)d_in[16];
    const float* attrv = (const float*)d_in[17];
    const float* concW = (const float*)d_in[18];
    const float* concb = (const float*)d_in[19];
    const float* outW  = (const float*)d_in[20];
    const float* outb  = (const float*)d_in[21];
    const float* gateW = (const float*)d_in[22];
    const float* gateb = (const float*)d_in[23];
    const float* projW = (const float*)d_in[24];
    const float* projb = (const float*)d_in[25];
    float* out = (float*)d_out;

    const long O_HID  = (long)M2*VV;
    const long O_AW1  = O_HID + (long)BB*HH;
    const long O_AW2  = O_AW1 + (long)BB*NN*TT;
    const long O_AW3  = O_AW2 + (long)BB*NN*SS;
    const long O_GATE = O_AW3 + (long)BB*NN*AA;

    float *p_emb, *p_gi;
    uint32_t *p_wt, *p_at;
    cudaGetSymbolAddress((void**)&p_emb,  g_emb);
    cudaGetSymbolAddress((void**)&p_gi,   g_gi);
    cudaGetSymbolAddress((void**)&p_wt,   g_wt);
    cudaGetSymbolAddress((void**)&p_at,   g_at);

    const int GRU_SMEM = (6144 + 16384 + 3072 + 16) * 4;   // ~100KB
    cudaFuncSetAttribute(k_gru_all, cudaFuncAttributeMaxDynamicSharedMemorySize, GRU_SMEM);
    const int CPK_SMEM = (10240 + 128*132) * 4;            // 108544
    cudaFuncSetAttribute(k_gemm_cpack, cudaFuncAttributeMaxDynamicSharedMemorySize, CPK_SMEM);

    // 1) embedding
    k_embed<<<(M2*HH + 255)/256, 256>>>(seq, emb);

    // 2) gi = embedded @ Wih^T + bih (split-tf32, fp32-accurate)
    k_gemm_tf32s<<<dim3((3*HH)/128, M2/128), 256>>>(p_emb, Wih, bih, p_gi, HH, 3*HH);

    // 3) mega kernel: GRU (128 blocks) + shadow work (pack_w, uvec, e4, chain) on 20 SMs
    k_gru_all<<<GRU_BLOCKS + SIDE_BLOCKS, 512, GRU_SMEM>>>(
        lasth, Whh, bhh, out + O_HID,
        outW, attnW, attnv, attnb, attrW, attrv, attrb, enc4, projW, projb, asp);

    // 4) scalar attention dots (+ flag reset in block 0)
    {
        int warps = M2 + TT*BB + SS*BB + AA*BB;
        k_ac<<<(warps*32 + 255)/256, 256>>>(enc1, enc2, enc3);
    }

    // 5) merged softmaxes
    k_softmax_all<<<BB*NN + 256 + 8, 256>>>(out + O_AW1, out + O_AW2, out + O_AW3);

    // 6) merged tail: ctx1/ctx2/ctx3 + gate (gate overlaps ctx)
    k_tail<<<2048, 256>>>(out + O_AW1, enc1, out + O_AW2, enc2, out + O_AW3, enc3,
                          gateW, gateb, out + O_GATE);

    // 7) concat GEMM with fused fragment pack -> packed tf32 big GEMM
    k_gemm_cpack<<<dim3(HH/128, M2/128), 128, CPK_SMEM>>>(concW, concb);
    k_gemm_tf32p<<<dim3(M2/128, VV/128), 128>>>((const uint4*)p_at, (const uint4*)p_wt, outb, out);

    // 8) deterministic scatter-add
    k_scatter<<<(int)(((long)M2*NASP + 255)/256), 256>>>(out + O_GATE, asp, out);
}

// round 17
// speedup vs baseline: 1.0985x; 1.0100x over previous
#include <cuda_runtime.h>
#include <cuda_bf16.h>
#include <math.h>
#include <stdint.h>

#define NN 64
#define BB 32
#define HH 512
#define KK 128
#define VV 32000
#define TT 256
#define SS 32
#define AA 5
#define AN 20
#define M2 (NN*BB)          // 2048 rows
#define CIN (3*HH+KK)       // 1664
#define GIN (2*HH+AN)       // 1044
#define NASP 2000
#define GRU_BLOCKS 128
#define SIDE_BLOCKS 20
#define UCOLS (2*HH + HH + KK)   // 1664 projected columns

// ---------------- scratch (static device globals; no runtime alloc) ----------------
__device__ __align__(16) float g_emb[M2*HH];
__device__ __align__(16) float g_gi[M2*3*HH];
__device__ __align__(16) float g_hA[HH*BB];
__device__ __align__(16) float g_hB[HH*BB];
__device__ __align__(16) float g_rnn[M2*HH];
__device__ __align__(16) float g_u1[HH];
__device__ __align__(16) float g_u1e[HH];
__device__ __align__(16) float g_u3[HH];
__device__ __align__(16) float g_u3e[KK];
__device__ float g_bv[2];
__device__ float g_a1[M2], g_a3[M2];
__device__ float g_c1[TT*BB], g_c2[SS*BB], g_c3[AA*BB];
__device__ __align__(16) float g_ctx1[M2*HH];
__device__ __align__(16) float g_ctx2[M2*HH];
__device__ __align__(16) float g_ctx3[M2*KK];
__device__ __align__(16) uint32_t g_wt[VV*HH];      // 65.5 MB pre-rounded, fragment-packed W
__device__ __align__(16) uint32_t g_at[M2*HH];      // 4 MB fragment-packed A
__device__ float g_e4[BB*AN];
__device__ int g_next[NASP];
__device__ int g_aspmap[VV];                        // vocab id -> first chain index (or -1)
__device__ __align__(128) unsigned g_flag[GRU_BLOCKS*32] = {0};

// ---------------- contention-free flag barrier (GRU blocks only; monotonic) ----------------
__device__ __forceinline__ void gru_barrier(int bk, unsigned step) {
    __syncthreads();
    if (threadIdx.x == 0) {
        asm volatile("st.release.gpu.global.u32 [%0], %1;"
                     :: "l"(&g_flag[bk*32]), "r"(step) : "memory");
    }
    if (threadIdx.x < GRU_BLOCKS) {
        unsigned v;
        do {
            asm volatile("ld.acquire.gpu.global.u32 %0, [%1];"
                         : "=r"(v) : "l"(&g_flag[threadIdx.x*32]) : "memory");
        } while (v < step);
    }
    __syncthreads();
}

// ---------------- helpers ----------------
__device__ __forceinline__ uint32_t smem_u32(const void* p) {
    uint32_t a;
    asm("{ .reg .u64 t; cvta.to.shared.u64 t, %1; cvt.u32.u64 %0, t; }" : "=r"(a) : "l"(p));
    return a;
}
__device__ __forceinline__ uint32_t f2tf(float x) {
    uint32_t u; asm("cvt.rna.tf32.f32 %0, %1;" : "=r"(u) : "f"(x)); return u;
}
__device__ __forceinline__ void split_tf32(float x, uint32_t& hi, uint32_t& lo) {
    hi = f2tf(x);
    float r = x - __uint_as_float(hi);
    lo = f2tf(r);
}
__device__ __forceinline__ void mma_tf32(float& c0, float& c1, float& c2, float& c3,
                                         uint32_t a0, uint32_t a1, uint32_t a2, uint32_t a3,
                                         uint32_t b0, uint32_t b1) {
    asm volatile("mma.sync.aligned.m16n8k8.row.col.f32.tf32.tf32.f32 "
                 "{%0,%1,%2,%3},{%4,%5,%6,%7},{%8,%9},{%0,%1,%2,%3};"
                 : "+f"(c0), "+f"(c1), "+f"(c2), "+f"(c3)
                 : "r"(a0), "r"(a1), "r"(a2), "r"(a3), "r"(b0), "r"(b1));
}
__device__ __forceinline__ void cpa16(uint32_t saddr, const void* gaddr) {
    asm volatile("cp.async.cg.shared.global [%0], [%1], 16;" :: "r"(saddr), "l"(gaddr));
}

// ---------------- kernels ----------------

__global__ void k_embed(const int* __restrict__ seq, const float* __restrict__ emb) {
    int i = blockIdx.x * blockDim.x + threadIdx.x;
    if (i < M2*HH) {
        int m = i / HH, h = i - m*HH;
        g_emb[i] = emb[(long)seq[m]*HH + h];
    }
}

// ---------------- packed tf32 GEMM + fused aspect scatter-add ----------------
__global__ __launch_bounds__(128, 2)
void k_gemm_tf32p(const uint4* __restrict__ At, const uint4* __restrict__ Wt,
                  const float* __restrict__ bias, float* __restrict__ C,
                  const float* __restrict__ gate) {
    __shared__ __align__(16) uint4 As[2][512];
    __shared__ __align__(16) uint4 Bs[2][512];
    int tid = threadIdx.x;
    int warp = tid >> 5, lane = tid & 31;
    int wm = warp & 1, wnp = warp >> 1;
    int lq = lane >> 2, lr = lane & 3;
    int m0 = blockIdx.x * 128, n0 = blockIdx.y * 128;
    const uint4* Ab = At + (long)blockIdx.x * 16384;
    const uint4* Bb = Wt + (long)blockIdx.y * 16384;

    float acc[4][8][4];
#pragma unroll
    for (int i = 0; i < 4; i++)
#pragma unroll
        for (int j = 0; j < 8; j++)
#pragma unroll
            for (int c = 0; c < 4; c++) acc[i][j][c] = 0.f;

#pragma unroll
    for (int i = 0; i < 4; i++) {
        cpa16(smem_u32(&As[0][i*128 + tid]), Ab + i*128 + tid);
        cpa16(smem_u32(&Bs[0][i*128 + tid]), Bb + i*128 + tid);
    }
    asm volatile("cp.async.commit_group;");

    int buf = 0;
    const int NK = HH / 16;
    for (int c = 0; c < NK; c++) {
        asm volatile("cp.async.wait_group 0;" ::: "memory");
        __syncthreads();
        if (c + 1 < NK) {
            const uint4* an = Ab + (c+1)*512;
            const uint4* bn = Bb + (c+1)*512;
#pragma unroll
            for (int i = 0; i < 4; i++) {
                cpa16(smem_u32(&As[buf^1][i*128 + tid]), an + i*128 + tid);
                cpa16(smem_u32(&Bs[buf^1][i*128 + tid]), bn + i*128 + tid);
            }
            asm volatile("cp.async.commit_group;");
        }
#pragma unroll
        for (int kk = 0; kk < 2; kk++) {
            uint4 av[4], bv[4];
#pragma unroll
            for (int ms = 0; ms < 4; ms++)
                av[ms] = As[buf][kk*256 + (wm*4 + ms)*32 + lane];
#pragma unroll
            for (int p = 0; p < 4; p++)
                bv[p] = Bs[buf][kk*256 + (wnp*4 + p)*32 + lane];
#pragma unroll
            for (int ms = 0; ms < 4; ms++)
#pragma unroll
                for (int p = 0; p < 4; p++) {
                    mma_tf32(acc[ms][2*p][0], acc[ms][2*p][1], acc[ms][2*p][2], acc[ms][2*p][3],
                             av[ms].x, av[ms].y, av[ms].z, av[ms].w, bv[p].x, bv[p].y);
                    mma_tf32(acc[ms][2*p+1][0], acc[ms][2*p+1][1], acc[ms][2*p+1][2], acc[ms][2*p+1][3],
                             av[ms].x, av[ms].y, av[ms].z, av[ms].w, bv[p].z, bv[p].w);
                }
        }
        buf ^= 1;
    }
#pragma unroll
    for (int ms = 0; ms < 4; ms++) {
        int row = m0 + wm*64 + ms*16 + lq;
#pragma unroll
        for (int ns = 0; ns < 8; ns++) {
            int col = n0 + wnp*64 + ns*8 + lr*2;
            float b0 = bias[col], b1 = bias[col+1];
            float v00 = acc[ms][ns][0] + b0, v01 = acc[ms][ns][1] + b1;
            float v10 = acc[ms][ns][2] + b0, v11 = acc[ms][ns][3] + b1;
            // fused aspect scatter-add (same chain order as reference scatter)
            int j0 = g_aspmap[col];
            if (j0 >= 0) {
                float sA = 0.f, sB = 0.f;
                int jj = j0;
                while (jj >= 0) {
                    int r = jj % AN;
                    sA += gate[(long)row*AN + r];
                    sB += gate[(long)(row+8)*AN + r];
                    jj = g_next[jj];
                }
                v00 += sA; v10 += sB;
            }
            int j1 = g_aspmap[col + 1];
            if (j1 >= 0) {
                float sA = 0.f, sB = 0.f;
                int jj = j1;
                while (jj >= 0) {
                    int r = jj % AN;
                    sA += gate[(long)row*AN + r];
                    sB += gate[(long)(row+8)*AN + r];
                    jj = g_next[jj];
                }
                v01 += sA; v11 += sB;
            }
            *(float2*)(C + (long)row*VV + col)     = make_float2(v00, v01);
            *(float2*)(C + (long)(row+8)*VV + col) = make_float2(v10, v11);
        }
    }
}

// ---------------- mega kernel: persistent GRU (0..127) + side work (128..147) ----------------
__global__ __launch_bounds__(512, 1)
void k_gru_all(const float* __restrict__ lasth, const float* __restrict__ Whh,
               const float* __restrict__ bhh, float* __restrict__ hid,
               const float* __restrict__ outW,
               const float* __restrict__ attnW, const float* __restrict__ attnv,
               const float* __restrict__ attnb, const float* __restrict__ attrW,
               const float* __restrict__ attrv, const float* __restrict__ attrb,
               const float* __restrict__ enc4, const float* __restrict__ projW,
               const float* __restrict__ projb, const int* __restrict__ asp) {
    extern __shared__ __align__(16) float dsm[];
    int tid = threadIdx.x, bk = blockIdx.x;

    if (bk >= GRU_BLOCKS) {
        // ===================== side work on 20 spare SMs =====================
        int sb = bk - GRU_BLOCKS;
        // (a) W fragment pack (grid-strided over side blocks)
        const long TOTW = (long)(VV/128)*64*8*32;
        for (long i = (long)sb*512 + tid; i < TOTW; i += (long)SIDE_BLOCKS*512) {
            int lane = (int)(i & 31), fp = (int)((i >> 5) & 7), s = (int)((i >> 8) & 63);
            long nb = i >> 14;
            int lq = lane >> 2, lr = lane & 3;
            int k = s*8 + lr;
            long ne = nb*128 + fp*16 + lq;
            uint4 v;
            v.x = f2tf(outW[ne*HH + k]);
            v.y = f2tf(outW[ne*HH + k + 4]);
            v.z = f2tf(outW[(ne+8)*HH + k]);
            v.w = f2tf(outW[(ne+8)*HH + k + 4]);
            ((uint4*)g_wt)[i] = v;
        }
        // (b) uvec: full-column warp dots
        {
            int gw2 = sb*16 + (tid >> 5);
            int lane = tid & 31;
            for (int t = gw2; t < UCOLS + 2; t += SIDE_BLOCKS*16) {
                float s = 0.f;
                if (t < UCOLS) {
                    const float* W; const float* v; int ld; int c;
                    if (t < 2*HH) { W = attnW; v = attnv; ld = 2*HH;    c = t; }
                    else          { W = attrW; v = attrv; ld = HH + KK; c = t - 2*HH; }
                    for (int h = lane; h < HH; h += 32) s += W[(long)h*ld + c]*v[h];
#pragma unroll
                    for (int o = 16; o > 0; o >>= 1) s += __shfl_xor_sync(0xffffffffu, s, o);
                    if (lane == 0) {
                        if (t < HH)            g_u1[t] = s;
                        else if (t < 2*HH)     g_u1e[t - HH] = s;
                        else if (t < 3*HH)     g_u3[t - 2*HH] = s;
                        else                   g_u3e[t - 3*HH] = s;
                    }
                } else {
                    int w = t - UCOLS;
                    const float* bp = w ? attrb : attnb;
                    const float* vp = w ? attrv : attnv;
                    for (int h = lane; h < HH; h += 32) s += bp[h]*vp[h];
#pragma unroll
                    for (int o = 16; o > 0; o >>= 1) s += __shfl_xor_sync(0xffffffffu, s, o);
                    if (lane == 0) g_bv[w] = s;
                }
            }
        }
        // (c) e4 projection (block sb==0)
        if (sb == 0) {
            for (int i = tid; i < BB*AN; i += 512) {
                int b = i / AN, j = i - b*AN;
                float s = projb[j];
                for (int k = 0; k < AN; k++) s += enc4[(0*BB + b)*AN + k]*projW[j*2*AN + k];
                for (int k = 0; k < AN; k++) s += enc4[(1*BB + b)*AN + k]*projW[j*2*AN + AN + k];
                g_e4[i] = s;
            }
        }
        // (d) duplicate-chain + aspmap (block sb==1)
        if (sb == 1) {
            int* sid = (int*)dsm;
            for (int k = tid; k < NASP; k += 512) sid[k] = asp[k];
            __syncthreads();
            for (int k = tid; k < VV; k += 512) g_aspmap[k] = -1;
            for (int j = tid; j < NASP; j += 512) {
                int v = sid[j];
                int fst = 1, nxt = -1;
                for (int j2 = 0; j2 < NASP; j2++) {
                    int w = sid[j2];
                    if (w == v) {
                        if (j2 < j) fst = 0;
                        else if (j2 > j && nxt < 0) nxt = j2;
                    }
                }
                g_next[j] = nxt;
                if (fst) g_aspmap[v] = j;
            }
        }
        return;
    }

    // ===================== persistent GRU =====================
    float* sw   = dsm;                    // 6144
    float* sh   = dsm + 6144;             // 16384
    float* part = dsm + 6144 + 16384;     // 3072
    float* sbv  = part + 3072;            // 12

    int b  = tid & 31;
    int ju = (tid >> 5) & 1;
    int kq = tid >> 6;

    for (int r = 0; r < 12; r++) {
        int g = r / 4, j = r % 4;
        int rowi = g*HH + bk*4 + j;
        for (int k = tid; k < HH; k += 512) sw[(g*4 + j)*HH + k] = Whh[(long)rowi*HH + k];
    }
    if (tid < 12) sbv[tid] = bhh[(tid/4)*HH + bk*4 + (tid%4)];

    if (tid < 128) {
        int idx = bk*128 + tid;
        int k = idx >> 5, bb = idx & 31;
        __stcg(&g_hA[idx], lasth[bb*HH + k]);
    }
    gru_barrier(bk, 1u);

    float* hp = g_hA;
    float* hc = g_hB;
    int u0 = ju*2;
    const float* wr0 = sw + (0*4 + u0    )*HH;
    const float* wr1 = sw + (0*4 + u0 + 1)*HH;
    const float* wz0 = sw + (1*4 + u0    )*HH;
    const float* wz1 = sw + (1*4 + u0 + 1)*HH;
    const float* wn0 = sw + (2*4 + u0    )*HH;
    const float* wn1 = sw + (2*4 + u0 + 1)*HH;
    int k0 = kq * 64;

    for (int n = 0; n < NN; n++) {
#pragma unroll
        for (int i = 0; i < 8; i++) {
            int f = tid + i*512;
            float4 v = __ldcg((const float4*)hp + f);
            *(float4*)(sh + 4*f) = v;
        }
        __syncthreads();

        float sr0 = 0.f, sz0 = 0.f, sn0 = 0.f;
        float sr1 = 0.f, sz1 = 0.f, sn1 = 0.f;
#pragma unroll 4
        for (int k = k0; k < k0 + 64; k += 4) {
            float h0 = sh[(k+0)*BB + b];
            float h1 = sh[(k+1)*BB + b];
            float h2 = sh[(k+2)*BB + b];
            float h3 = sh[(k+3)*BB + b];
            float4 a;
            a = *(const float4*)(wr0 + k); sr0 += a.x*h0 + a.y*h1 + a.z*h2 + a.w*h3;
            a = *(const float4*)(wz0 + k); sz0 += a.x*h0 + a.y*h1 + a.z*h2 + a.w*h3;
            a = *(const float4*)(wn0 + k); sn0 += a.x*h0 + a.y*h1 + a.z*h2 + a.w*h3;
            a = *(const float4*)(wr1 + k); sr1 += a.x*h0 + a.y*h1 + a.z*h2 + a.w*h3;
            a = *(const float4*)(wz1 + k); sz1 += a.x*h0 + a.y*h1 + a.z*h2 + a.w*h3;
            a = *(const float4*)(wn1 + k); sn1 += a.x*h0 + a.y*h1 + a.z*h2 + a.w*h3;
        }
        part[((0*4 + u0    )*8 + kq)*32 + b] = sr0;
        part[((1*4 + u0    )*8 + kq)*32 + b] = sz0;
        part[((2*4 + u0    )*8 + kq)*32 + b] = sn0;
        part[((0*4 + u0 + 1)*8 + kq)*32 + b] = sr1;
        part[((1*4 + u0 + 1)*8 + kq)*32 + b] = sz1;
        part[((2*4 + u0 + 1)*8 + kq)*32 + b] = sn1;
        __syncthreads();

        if (kq < 2) {
            int jgl = u0 + kq;
            int jg  = bk*4 + jgl;
            float sr = 0.f, sz = 0.f, sn = 0.f;
#pragma unroll
            for (int q = 0; q < 8; q++) {
                sr += part[((0*4 + jgl)*8 + q)*32 + b];
                sz += part[((1*4 + jgl)*8 + q)*32 + b];
                sn += part[((2*4 + jgl)*8 + q)*32 + b];
            }
            float hold = sh[jg*BB + b];
            const float* gi = g_gi + ((long)(n*BB + b))*(3*HH);
            float rr = 1.f/(1.f + expf(-(gi[jg]        + sr + sbv[0*4 + jgl])));
            float zz = 1.f/(1.f + expf(-(gi[HH + jg]   + sz + sbv[1*4 + jgl])));
            float nn = tanhf(gi[2*HH + jg] + rr*(sn + sbv[2*4 + jgl]));
            float hn = (1.f - zz)*nn + zz*hold;
            __stcg(hc + jg*BB + b, hn);
            g_rnn[((long)(n*BB + b))*HH + jg] = hn;
            if (n == NN-1) hid[b*HH + jg] = hn;
        }
        if (n < NN-1) gru_barrier(bk, (unsigned)(n + 2));
        float* t = hp; hp = hc; hc = t;
    }
}

// ---------------- concat tf32 GEMM with FUSED fragment pack (writes g_at directly) ----------------
__device__ __forceinline__ const float* concat_src(int m, int k) {
    if (k < HH)        return g_rnn  + (long)m*HH + k;
    if (k < 2*HH)      return g_ctx1 + (long)m*HH + (k - HH);
    if (k < 3*HH)      return g_ctx2 + (long)m*HH + (k - 2*HH);
    return g_ctx3 + (long)m*KK + (k - 3*HH);
}

__global__ __launch_bounds__(128, 1)
void k_gemm_cpack(const float* __restrict__ W, const float* __restrict__ bias) {
    extern __shared__ __align__(16) float ds2[];
    float* AsB = ds2;                 // As: [2][128][20]
    float* BsB = ds2 + 5120;
    float* tile = ds2 + 10240;        // [128][132]
    int tid = threadIdx.x;
    int warp = tid >> 5, lane = tid & 31;
    int wm = warp & 1, wnp = warp >> 1;
    int lq = lane >> 2, lr = lane & 3;
    int m0 = blockIdx.y * 128, n0 = blockIdx.x * 128;

    float acc[4][8][4];
#pragma unroll
    for (int i = 0; i < 4; i++)
#pragma unroll
        for (int j = 0; j < 8; j++)
#pragma unroll
            for (int c = 0; c < 4; c++) acc[i][j][c] = 0.f;

    const int NK = CIN / 16;
#pragma unroll
    for (int i = 0; i < 4; i++) {
        int idx = i*128 + tid, row = idx >> 2, kc = idx & 3;
        cpa16(smem_u32(&AsB[(0*128 + row)*20 + kc*4]), concat_src(m0+row, kc*4));
        cpa16(smem_u32(&BsB[(0*128 + row)*20 + kc*4]), W + (long)(n0+row)*CIN + kc*4);
    }
    asm volatile("cp.async.commit_group;");

    int buf = 0;
    for (int ks = 0; ks < NK; ks++) {
        asm volatile("cp.async.wait_group 0;");
        __syncthreads();
        if (ks + 1 < NK) {
#pragma unroll
            for (int i = 0; i < 4; i++) {
                int idx = i*128 + tid, row = idx >> 2, kc = idx & 3;
                int kpos = (ks+1)*16 + kc*4;
                cpa16(smem_u32(&AsB[((buf^1)*128 + row)*20 + kc*4]), concat_src(m0+row, kpos));
                cpa16(smem_u32(&BsB[((buf^1)*128 + row)*20 + kc*4]), W + (long)(n0+row)*CIN + kpos);
            }
            asm volatile("cp.async.commit_group;");
        }
#pragma unroll
        for (int kk = 0; kk < 16; kk += 8) {
            uint32_t af[4][4], bf[8][2];
#pragma unroll
            for (int ms = 0; ms < 4; ms++) {
                int rb = wm*64 + ms*16;
                af[ms][0] = f2tf(AsB[(buf*128 + rb + lq    )*20 + kk + lr    ]);
                af[ms][1] = f2tf(AsB[(buf*128 + rb + lq + 8)*20 + kk + lr    ]);
                af[ms][2] = f2tf(AsB[(buf*128 + rb + lq    )*20 + kk + lr + 4]);
                af[ms][3] = f2tf(AsB[(buf*128 + rb + lq + 8)*20 + kk + lr + 4]);
            }
#pragma unroll
            for (int ns = 0; ns < 8; ns++) {
                int nb = wnp*64 + ns*8;
                bf[ns][0] = f2tf(BsB[(buf*128 + nb + lq)*20 + kk + lr    ]);
                bf[ns][1] = f2tf(BsB[(buf*128 + nb + lq)*20 + kk + lr + 4]);
            }
#pragma unroll
            for (int ms = 0; ms < 4; ms++)
#pragma unroll
                for (int ns = 0; ns < 8; ns++)
                    mma_tf32(acc[ms][ns][0], acc[ms][ns][1], acc[ms][ns][2], acc[ms][ns][3],
                             af[ms][0], af[ms][1], af[ms][2], af[ms][3],
                             bf[ns][0], bf[ns][1]);
        }
        buf ^= 1;
    }
#pragma unroll
    for (int ms = 0; ms < 4; ms++) {
        int lrow = wm*64 + ms*16 + lq;
#pragma unroll
        for (int ns = 0; ns < 8; ns++) {
            int lcol = wnp*64 + ns*8 + lr*2;
            float b0 = bias[n0 + lcol], b1 = bias[n0 + lcol + 1];
            tile[lrow*132 + lcol]       = tanhf(acc[ms][ns][0] + b0);
            tile[lrow*132 + lcol + 1]   = tanhf(acc[ms][ns][1] + b1);
            tile[(lrow+8)*132 + lcol]   = tanhf(acc[ms][ns][2] + b0);
            tile[(lrow+8)*132 + lcol+1] = tanhf(acc[ms][ns][3] + b1);
        }
    }
    __syncthreads();
    int mb = blockIdx.y, xb = blockIdx.x;
    for (int t = tid; t < 4096; t += 128) {
        int ln = t & 31, fp = (t >> 5) & 7, sl = t >> 8;
        int lq2 = ln >> 2, lr2 = ln & 3;
        uint4 v;
        v.x = f2tf(tile[(fp*16 + lq2    )*132 + sl*8 + lr2    ]);
        v.y = f2tf(tile[(fp*16 + lq2 + 8)*132 + sl*8 + lr2    ]);
        v.z = f2tf(tile[(fp*16 + lq2    )*132 + sl*8 + lr2 + 4]);
        v.w = f2tf(tile[(fp*16 + lq2 + 8)*132 + sl*8 + lr2 + 4]);
        ((uint4*)g_at)[(((long)mb*64 + xb*16 + sl)*8 + fp)*32 + ln] = v;
    }
}

// split-precision tf32 GEMM (fp32-accurate) for gi
__global__ __launch_bounds__(256)
void k_gemm_tf32s(const float* __restrict__ A, const float* __restrict__ W,
                  const float* __restrict__ bias, float* __restrict__ C,
                  int Kd, int ldC) {
    __shared__ __align__(16) float As[2][128][20];
    __shared__ __align__(16) float Bs[2][128][20];
    int tid = threadIdx.x;
    int warp = tid >> 5, lane = tid & 31;
    int wm = warp & 1, wn = warp >> 1;
    int lq = lane >> 2, lr = lane & 3;
    int m0 = blockIdx.y * 128, n0 = blockIdx.x * 128;

    float acc[4][4][4];
#pragma unroll
    for (int i = 0; i < 4; i++)
#pragma unroll
        for (int j = 0; j < 4; j++)
#pragma unroll
            for (int c = 0; c < 4; c++) acc[i][j][c] = 0.f;

    const int NK = Kd / 16;
#pragma unroll
    for (int i = 0; i < 2; i++) {
        int idx = i*256 + tid, row = idx >> 2, kc = idx & 3;
        cpa16(smem_u32(&As[0][row][kc*4]), A + (long)(m0+row)*Kd + kc*4);
        cpa16(smem_u32(&Bs[0][row][kc*4]), W + (long)(n0+row)*Kd + kc*4);
    }
    asm volatile("cp.async.commit_group;");

    int buf = 0;
    for (int ks = 0; ks < NK; ks++) {
        asm volatile("cp.async.wait_group 0;");
        __syncthreads();
        if (ks + 1 < NK) {
#pragma unroll
            for (int i = 0; i < 2; i++) {
                int idx = i*256 + tid, row = idx >> 2, kc = idx & 3;
                int kpos = (ks+1)*16 + kc*4;
                cpa16(smem_u32(&As[buf^1][row][kc*4]), A + (long)(m0+row)*Kd + kpos);
                cpa16(smem_u32(&Bs[buf^1][row][kc*4]), W + (long)(n0+row)*Kd + kpos);
            }
            asm volatile("cp.async.commit_group;");
        }
#pragma unroll
        for (int kk = 0; kk < 16; kk += 8) {
            uint32_t ah[4][4], al[4][4], bh[4][2], bl[4][2];
#pragma unroll
            for (int ms = 0; ms < 4; ms++) {
                int rb = wm*64 + ms*16;
                split_tf32(As[buf][rb + lq    ][kk + lr    ], ah[ms][0], al[ms][0]);
                split_tf32(As[buf][rb + lq + 8][kk + lr    ], ah[ms][1], al[ms][1]);
                split_tf32(As[buf][rb + lq    ][kk + lr + 4], ah[ms][2], al[ms][2]);
                split_tf32(As[buf][rb + lq + 8][kk + lr + 4], ah[ms][3], al[ms][3]);
            }
#pragma unroll
            for (int ns = 0; ns < 4; ns++) {
                int nb = wn*32 + ns*8;
                split_tf32(Bs[buf][nb + lq][kk + lr    ], bh[ns][0], bl[ns][0]);
                split_tf32(Bs[buf][nb + lq][kk + lr + 4], bh[ns][1], bl[ns][1]);
            }
#pragma unroll
            for (int ms = 0; ms < 4; ms++)
#pragma unroll
                for (int ns = 0; ns < 4; ns++) {
                    mma_tf32(acc[ms][ns][0], acc[ms][ns][1], acc[ms][ns][2], acc[ms][ns][3],
                             ah[ms][0], ah[ms][1], ah[ms][2], ah[ms][3], bh[ns][0], bh[ns][1]);
                    mma_tf32(acc[ms][ns][0], acc[ms][ns][1], acc[ms][ns][2], acc[ms][ns][3],
                             ah[ms][0], ah[ms][1], ah[ms][2], ah[ms][3], bl[ns][0], bl[ns][1]);
                    mma_tf32(acc[ms][ns][0], acc[ms][ns][1], acc[ms][ns][2], acc[ms][ns][3],
                             al[ms][0], al[ms][1], al[ms][2], al[ms][3], bh[ns][0], bh[ns][1]);
                }
        }
        buf ^= 1;
    }
#pragma unroll
    for (int ms = 0; ms < 4; ms++) {
        int row = m0 + wm*64 + ms*16 + lq;
#pragma unroll
        for (int ns = 0; ns < 4; ns++) {
            int col = n0 + wn*32 + ns*8 + lr*2;
            float b0 = bias[col], b1 = bias[col+1];
            *(float2*)(C + (long)row*ldC + col)     = make_float2(acc[ms][ns][0] + b0, acc[ms][ns][1] + b1);
            *(float2*)(C + (long)(row+8)*ldC + col) = make_float2(acc[ms][ns][2] + b0, acc[ms][ns][3] + b1);
        }
    }
}

// all scalar attention dot products (a-dots + c-dots); block 0 also resets GRU flags
__global__ void k_ac(const float* __restrict__ enc1, const float* __restrict__ enc2,
                     const float* __restrict__ enc3) {
    if (blockIdx.x == 0 && threadIdx.x < GRU_BLOCKS) g_flag[threadIdx.x*32] = 0u;
    int gw = (blockIdx.x * blockDim.x + threadIdx.x) >> 5;
    int lane = threadIdx.x & 31;
    const int E_A = M2, E_C1 = E_A + TT*BB, E_C2 = E_C1 + SS*BB, E_C3 = E_C2 + AA*BB;
    if (gw >= E_C3) return;
    if (gw < E_A) {
        const float4* x = (const float4*)(g_rnn + (long)gw*HH);
        const float4* u1 = (const float4*)g_u1;
        const float4* u3 = (const float4*)g_u3;
        float s1 = 0.f, s3 = 0.f;
#pragma unroll
        for (int k = lane; k < HH/4; k += 32) {
            float4 xv = x[k], a = u1[k], b = u3[k];
            s1 += xv.x*a.x + xv.y*a.y + xv.z*a.z + xv.w*a.w;
            s3 += xv.x*b.x + xv.y*b.y + xv.z*b.z + xv.w*b.w;
        }
#pragma unroll
        for (int o = 16; o > 0; o >>= 1) {
            s1 += __shfl_xor_sync(0xffffffffu, s1, o);
            s3 += __shfl_xor_sync(0xffffffffu, s3, o);
        }
        if (lane == 0) { g_a1[gw] = s1 + g_bv[0]; g_a3[gw] = s3 + g_bv[1]; }
        return;
    }
    const float* x; const float* u; float* dst; int len = HH;
    if (gw < E_C1)      { int m = gw - E_A;   x = enc1 + (long)m*HH; u = g_u1e; dst = g_c1 + m; }
    else if (gw < E_C2) { int m = gw - E_C1;  x = enc2 + (long)m*HH; u = g_u1e; dst = g_c2 + m; }
    else                { int m = gw - E_C2;  x = enc3 + (long)m*KK; u = g_u3e; dst = g_c3 + m; len = KK; }
    const float4* x4 = (const float4*)x;
    const float4* u4 = (const float4*)u;
    float s = 0.f;
    for (int k = lane; k < len/4; k += 32) {
        float4 xv = x4[k], uv = u4[k];
        s += xv.x*uv.x + xv.y*uv.y + xv.z*uv.z + xv.w*uv.w;
    }
#pragma unroll
    for (int o = 16; o > 0; o >>= 1) s += __shfl_xor_sync(0xffffffffu, s, o);
    if (lane == 0) *dst = s;
}

// merged softmaxes
__global__ void k_softmax_all(float* __restrict__ aw1, float* __restrict__ aw2,
                              float* __restrict__ aw3) {
    int blk = blockIdx.x;
    int tid = threadIdx.x;
    if (blk < BB*NN) {
        int bn = blk;
        int b = bn / NN, n = bn - b*NN;
        float e  = tanhf(g_a1[n*BB + b] + g_c1[tid*BB + b]);
        float ex = expf(e);
        __shared__ float red[8];
        __shared__ float stot;
        float s = ex;
#pragma unroll
        for (int o = 16; o > 0; o >>= 1) s += __shfl_xor_sync(0xffffffffu, s, o);
        if ((tid & 31) == 0) red[tid >> 5] = s;
        __syncthreads();
        if (tid == 0) { float tt = 0.f; for (int i = 0; i < 8; i++) tt += red[i]; stot = tt; }
        __syncthreads();
        aw1[(long)bn*TT + tid] = ex / stot;
    } else if (blk < BB*NN + 256) {
        int gw = (blk - BB*NN)*8 + (tid >> 5);
        int b = gw / NN, n = gw - b*NN;
        int s2 = tid & 31;
        float e  = tanhf(g_a1[n*BB + b] + g_c2[s2*BB + b]);
        float ex = expf(e);
        float tot = ex;
#pragma unroll
        for (int o = 16; o > 0; o >>= 1) tot += __shfl_xor_sync(0xffffffffu, tot, o);
        aw2[(long)gw*SS + s2] = ex / tot;
    } else {
        int bn = (blk - BB*NN - 256)*256 + tid;
        if (bn >= BB*NN) return;
        int b = bn / NN, n = bn - b*NN;
        float ex[AA]; float tot = 0.f;
#pragma unroll
        for (int a = 0; a < AA; a++) {
            ex[a] = expf(tanhf(g_a3[n*BB + b] + g_c3[a*BB + b]));
            tot += ex[a];
        }
#pragma unroll
        for (int a = 0; a < AA; a++) aw3[(long)bn*AA + a] = ex[a] / tot;
    }
}

// ---------------- merged tail: ctx1/ctx2 (tiled), ctx3 (naive), gate ----------------
__global__ __launch_bounds__(256)
void k_tail(const float* __restrict__ aw1, const float* __restrict__ enc1,
            const float* __restrict__ aw2, const float* __restrict__ enc2,
            const float* __restrict__ aw3, const float* __restrict__ enc3,
            const float* __restrict__ gateW, const float* __restrict__ gateb,
            float* __restrict__ gateout) {
    __shared__ __align__(16) char sbuf[17280];
    int blk = blockIdx.x;
    int tid = threadIdx.x;

    if (blk < 512) {
        const float* aw  = (blk < 256) ? aw1 : aw2;
        const float* enc = (blk < 256) ? enc1 : enc2;
        float* dst = (blk < 256) ? g_ctx1 : g_ctx2;
        int L = (blk < 256) ? TT : SS;
        int lb = blk & 255;
        int b  = lb & 31;
        int h0 = (lb >> 5) * 64;
        float (*AWs)[33] = (float(*)[33])sbuf;
        float (*Es)[68]  = (float(*)[68])(sbuf + 8448);
        int tx = tid & 15, ty = tid >> 4;
        float acc[4][4] = {};
        for (int t0 = 0; t0 < L; t0 += 32) {
            {
                int row = tid >> 2, c0 = (tid & 3) * 8;
                const float* ap = aw + ((long)b*NN + row)*L + t0 + c0;
                float4 v0 = *(const float4*)ap;
                float4 v1 = *(const float4*)(ap + 4);
                AWs[row][c0+0]=v0.x; AWs[row][c0+1]=v0.y; AWs[row][c0+2]=v0.z; AWs[row][c0+3]=v0.w;
                AWs[row][c0+4]=v1.x; AWs[row][c0+5]=v1.y; AWs[row][c0+6]=v1.z; AWs[row][c0+7]=v1.w;
            }
            {
                int row = tid >> 3, c0 = (tid & 7) * 8;
                const float* ep = enc + (((long)(t0+row))*BB + b)*HH + h0 + c0;
                float4 v0 = *(const float4*)ep;
                float4 v1 = *(const float4*)(ep + 4);
                Es[row][c0+0]=v0.x; Es[row][c0+1]=v0.y; Es[row][c0+2]=v0.z; Es[row][c0+3]=v0.w;
                Es[row][c0+4]=v1.x; Es[row][c0+5]=v1.y; Es[row][c0+6]=v1.z; Es[row][c0+7]=v1.w;
            }
            __syncthreads();
#pragma unroll
            for (int tt = 0; tt < 32; tt++) {
                float a[4], e[4];
#pragma unroll
                for (int i = 0; i < 4; i++) { a[i] = AWs[ty*4+i][tt]; e[i] = Es[tt][tx*4+i]; }
#pragma unroll
                for (int i = 0; i < 4; i++)
#pragma unroll
                    for (int j = 0; j < 4; j++) acc[i][j] += a[i]*e[j];
            }
            __syncthreads();
        }
#pragma unroll
        for (int i = 0; i < 4; i++) {
            int n = ty*4 + i;
#pragma unroll
            for (int j = 0; j < 4; j++)
                dst[(((long)n)*BB + b)*HH + h0 + tx*4 + j] = acc[i][j];
        }
    } else if (blk < 1536) {
        int i = (blk - 512)*256 + tid;
        if (i >= M2*KK) return;
        int m = i / KK, h = i - m*KK;
        int n = m / BB, b = m - n*BB;
        const float* awp = aw3 + ((long)b*NN + n)*AA;
        float s = 0.f;
        for (int t = 0; t < AA; t++) s += awp[t]*enc3[((long)t*BB + b)*KK + h];
        g_ctx3[i] = s;
    } else {
        int m0 = (blk - 1536)*4;
        float (*xs)[GIN + 12] = (float(*)[GIN + 12])sbuf;
#pragma unroll
        for (int r = 0; r < 4; r++) {
            int m = m0 + r, b = m & 31;
            for (int k = tid; k < GIN; k += 256) {
                float v;
                if (k < HH)        v = g_emb[(long)m*HH + k];
                else if (k < 2*HH) v = g_rnn[(long)m*HH + k - HH];
                else               v = g_e4[b*AN + k - 2*HH];
                xs[r][k] = v;
            }
        }
        __syncthreads();
        int w = tid >> 5, lane = tid & 31;
        for (int o = w; o < 4*AN; o += 8) {
            int r = o & 3, j = o >> 2;
            const float* wj = gateW + (long)j*GIN;
            float s = 0.f;
            for (int k = lane; k < GIN; k += 32) s += xs[r][k]*wj[k];
#pragma unroll
            for (int of = 16; of > 0; of >>= 1) s += __shfl_xor_sync(0xffffffffu, s, of);
            if (lane == 0) gateout[(long)(m0+r)*AN + j] = tanhf(s + gateb[j]);
        }
    }
}

// ---------------- launcher ----------------
extern "C" void kernel_launch(void* const* d_in, const int* in_sizes, int n_in,
                              void* d_out, int out_size) {
    const int*   seq   = (const int*)  d_in[0];
    const float* lasth = (const float*)d_in[1];
    const float* enc1  = (const float*)d_in[2];
    const float* enc2  = (const float*)d_in[3];
    const float* enc3  = (const float*)d_in[4];
    const float* enc4  = (const float*)d_in[5];
    const int*   asp   = (const int*)  d_in[6];
    const float* emb   = (const float*)d_in[7];
    const float* Wih   = (const float*)d_in[8];
    const float* Whh   = (const float*)d_in[9];
    const float* bih   = (const float*)d_in[10];
    const float* bhh   = (const float*)d_in[11];
    const float* attnW = (const float*)d_in[12];
    const float* attnb = (const float*)d_in[13];
    const float* attnv = (const float*)d_in[14];
    const float* attrW = (const float*)d_in[15];
    const float* attrb = (const float*)d_in[16];
    const float* attrv = (const float*)d_in[17];
    const float* concW = (const float*)d_in[18];
    const float* concb = (const float*)d_in[19];
    const float* outW  = (const float*)d_in[20];
    const float* outb  = (const float*)d_in[21];
    const float* gateW = (const float*)d_in[22];
    const float* gateb = (const float*)d_in[23];
    const float* projW = (const float*)d_in[24];
    const float* projb = (const float*)d_in[25];
    float* out = (float*)d_out;

    const long O_HID  = (long)M2*VV;
    const long O_AW1  = O_HID + (long)BB*HH;
    const long O_AW2  = O_AW1 + (long)BB*NN*TT;
    const long O_AW3  = O_AW2 + (long)BB*NN*SS;
    const long O_GATE = O_AW3 + (long)BB*NN*AA;

    float *p_emb, *p_gi;
    uint32_t *p_wt, *p_at;
    cudaGetSymbolAddress((void**)&p_emb,  g_emb);
    cudaGetSymbolAddress((void**)&p_gi,   g_gi);
    cudaGetSymbolAddress((void**)&p_wt,   g_wt);
    cudaGetSymbolAddress((void**)&p_at,   g_at);

    const int GRU_SMEM = (6144 + 16384 + 3072 + 16) * 4;   // ~100KB
    cudaFuncSetAttribute(k_gru_all, cudaFuncAttributeMaxDynamicSharedMemorySize, GRU_SMEM);
    const int CPK_SMEM = (10240 + 128*132) * 4;            // 108544
    cudaFuncSetAttribute(k_gemm_cpack, cudaFuncAttributeMaxDynamicSharedMemorySize, CPK_SMEM);

    // 1) embedding
    k_embed<<<(M2*HH + 255)/256, 256>>>(seq, emb);

    // 2) gi = embedded @ Wih^T + bih (split-tf32, fp32-accurate)
    k_gemm_tf32s<<<dim3((3*HH)/128, M2/128), 256>>>(p_emb, Wih, bih, p_gi, HH, 3*HH);

    // 3) mega kernel: GRU (128 blocks) + shadow work (pack_w, uvec, e4, chain+aspmap) on 20 SMs
    k_gru_all<<<GRU_BLOCKS + SIDE_BLOCKS, 512, GRU_SMEM>>>(
        lasth, Whh, bhh, out + O_HID,
        outW, attnW, attnv, attnb, attrW, attrv, attrb, enc4, projW, projb, asp);

    // 4) scalar attention dots (+ flag reset in block 0)
    {
        int warps = M2 + TT*BB + SS*BB + AA*BB;
        k_ac<<<(warps*32 + 255)/256, 256>>>(enc1, enc2, enc3);
    }

    // 5) merged softmaxes
    k_softmax_all<<<BB*NN + 256 + 8, 256>>>(out + O_AW1, out + O_AW2, out + O_AW3);

    // 6) merged tail: ctx1/ctx2/ctx3 + gate
    k_tail<<<2048, 256>>>(out + O_AW1, enc1, out + O_AW2, enc2, out + O_AW3, enc3,
                          gateW, gateb, out + O_GATE);

    // 7) concat GEMM with fused fragment pack -> packed tf32 big GEMM (+fused scatter-add)
    k_gemm_cpack<<<dim3(HH/128, M2/128), 128, CPK_SMEM>>>(concW, concb);
    k_gemm_tf32p<<<dim3(M2/128, VV/128), 128>>>((const uint4*)p_at, (const uint4*)p_wt,
                                                outb, out, out + O_GATE);
}